// round 1
// baseline (speedup 1.0000x reference)
#include <cuda_runtime.h>
#include <math.h>

#define N_TOK 2048
#define D_IN  1024
#define NH    16
#define E     64

// Scratch (allocation-free: __device__ globals)
__device__ float g_Q[NH * N_TOK * E];
__device__ float g_K[NH * N_TOK * E];
__device__ float g_V[NH * N_TOK * E];
__device__ float g_ctx[N_TOK * D_IN];

// ---------------------------------------------------------------------------
// Kernel 1: per-head QKV projection.  Q[h] = x @ Wq[h]  (2048x1024 @ 1024x64)
// grid = (32 m-tiles, 16 heads, 3 {q,k,v}); block = 256 threads; 64x64 tile.
// ---------------------------------------------------------------------------
__global__ __launch_bounds__(256) void qkv_kernel(
    const float* __restrict__ x,
    const float* __restrict__ Wq,
    const float* __restrict__ Wk,
    const float* __restrict__ Wv)
{
    __shared__ float As[32 * 65];   // A transposed: As[k][r], pad 65
    __shared__ float Bs[32 * 64];   // B natural:    Bs[k][e]

    const int tid = threadIdx.x;
    const int h   = blockIdx.y;
    const int sel = blockIdx.z;
    const float* W = (sel == 0 ? Wq : (sel == 1 ? Wk : Wv)) + (size_t)h * D_IN * E;
    float*     Out = (sel == 0 ? g_Q : (sel == 1 ? g_K : g_V)) + (size_t)h * N_TOK * E;

    const int m0 = blockIdx.x * 64;
    const int tr = tid >> 4, tc = tid & 15;
    const int r0 = tr * 4,   c0 = tc * 4;

    float acc[4][4] = {};

    for (int k0 = 0; k0 < D_IN; k0 += 32) {
        #pragma unroll
        for (int i = 0; i < 8; i++) {
            int idx = tid + i * 256;          // 64 rows x 32 cols
            int r = idx >> 5, k = idx & 31;
            As[k * 65 + r] = x[(size_t)(m0 + r) * D_IN + k0 + k];
        }
        #pragma unroll
        for (int i = 0; i < 8; i++) {
            int idx = tid + i * 256;          // 32 rows x 64 cols
            int k = idx >> 6, e = idx & 63;
            Bs[k * 64 + e] = W[(size_t)(k0 + k) * E + e];
        }
        __syncthreads();

        #pragma unroll
        for (int k = 0; k < 32; k++) {
            float a[4], b[4];
            #pragma unroll
            for (int u = 0; u < 4; u++) a[u] = As[k * 65 + r0 + u];
            #pragma unroll
            for (int u = 0; u < 4; u++) b[u] = Bs[k * 64 + c0 + u];
            #pragma unroll
            for (int u = 0; u < 4; u++)
                #pragma unroll
                for (int v = 0; v < 4; v++)
                    acc[u][v] = fmaf(a[u], b[v], acc[u][v]);
        }
        __syncthreads();
    }

    #pragma unroll
    for (int u = 0; u < 4; u++)
        #pragma unroll
        for (int v = 0; v < 4; v++)
            Out[(size_t)(m0 + r0 + u) * E + c0 + v] = acc[u][v];
}

// ---------------------------------------------------------------------------
// Kernel 2: flash attention per head. BQ = BK = 64, d = 64, online softmax.
// grid = (32 q-tiles, 16 heads); block = 256 threads; dynamic smem.
// ---------------------------------------------------------------------------
#define ATTN_SMEM_FLOATS (4160 /*Q*/ + 4160 /*K*/ + 4096 /*V*/ + 4160 /*P*/ + 64*3 + 256)

__global__ __launch_bounds__(256) void attn_kernel()
{
    extern __shared__ float sm[];
    float* Qs  = sm;                 // Qst[e][r]  [64][65]
    float* Ks  = Qs + 64 * 65;       // Kst[e][j]  [64][65]
    float* Vs  = Ks + 64 * 65;       // Vs[j][e]   [64][64]
    float* Ps  = Vs + 64 * 64;       // Pst[j][i]  [64][65]
    float* m_s = Ps + 64 * 65;       // [64]
    float* l_s = m_s + 64;           // [64]
    float* a_s = l_s + 64;           // [64] alpha
    float* red = a_s + 64;           // [4][64]

    const int tid = threadIdx.x;
    const int h   = blockIdx.y;
    const int q0  = blockIdx.x * 64;
    const int tr  = tid >> 4, tc = tid & 15;
    const int r0  = tr * 4,   c0 = tc * 4;
    const float scale = 0.125f;      // 1/sqrt(64)

    const float* Qg = g_Q + ((size_t)h * N_TOK + q0) * E;

    #pragma unroll
    for (int i = 0; i < 16; i++) {
        int idx = tid + i * 256;     // 64 rows x 64 cols, coalesced over e
        int r = idx >> 6, e = idx & 63;
        Qs[e * 65 + r] = Qg[idx];
    }
    if (tid < 64) { m_s[tid] = -INFINITY; l_s[tid] = 0.f; }

    float o[4][4] = {};
    __syncthreads();

    for (int kt = 0; kt < N_TOK; kt += 64) {
        const float* Kg = g_K + ((size_t)h * N_TOK + kt) * E;
        const float* Vg = g_V + ((size_t)h * N_TOK + kt) * E;
        #pragma unroll
        for (int i = 0; i < 16; i++) {
            int idx = tid + i * 256;
            int r = idx >> 6, e = idx & 63;
            Ks[e * 65 + r] = Kg[idx];
            Vs[idx]        = Vg[idx];
        }
        __syncthreads();

        // S = Q K^T (4x4 per thread)
        float s[4][4] = {};
        #pragma unroll
        for (int e = 0; e < 64; e++) {
            float a[4], b[4];
            #pragma unroll
            for (int u = 0; u < 4; u++) a[u] = Qs[e * 65 + r0 + u];
            #pragma unroll
            for (int u = 0; u < 4; u++) b[u] = Ks[e * 65 + c0 + u];
            #pragma unroll
            for (int u = 0; u < 4; u++)
                #pragma unroll
                for (int v = 0; v < 4; v++)
                    s[u][v] = fmaf(a[u], b[v], s[u][v]);
        }
        // stage S (scaled) transposed: Ps[j][i]
        #pragma unroll
        for (int u = 0; u < 4; u++)
            #pragma unroll
            for (int v = 0; v < 4; v++)
                Ps[(c0 + v) * 65 + (r0 + u)] = s[u][v] * scale;
        __syncthreads();

        // per-row max (partial over 16 j's per thread)
        {
            int i = tid & 63, qd = tid >> 6;
            float pm = -INFINITY;
            #pragma unroll
            for (int j = 0; j < 16; j++)
                pm = fmaxf(pm, Ps[(qd * 16 + j) * 65 + i]);
            red[qd * 64 + i] = pm;
        }
        __syncthreads();
        if (tid < 64) {
            float mt = fmaxf(fmaxf(red[tid], red[64 + tid]),
                             fmaxf(red[128 + tid], red[192 + tid]));
            float mo = m_s[tid];
            float mn = fmaxf(mo, mt);
            a_s[tid] = __expf(mo - mn);
            m_s[tid] = mn;
        }
        __syncthreads();
        // exponentiate in place + partial row sums
        {
            int i = tid & 63, qd = tid >> 6;
            float mi = m_s[i];
            float ps = 0.f;
            #pragma unroll
            for (int j = 0; j < 16; j++) {
                float* p = &Ps[(qd * 16 + j) * 65 + i];
                float v = __expf(*p - mi);
                *p = v; ps += v;
            }
            red[qd * 64 + i] = ps;
        }
        __syncthreads();
        if (tid < 64) {
            float rs = red[tid] + red[64 + tid] + red[128 + tid] + red[192 + tid];
            l_s[tid] = l_s[tid] * a_s[tid] + rs;
        }
        __syncthreads();

        // O = O*alpha + P @ V
        float al[4];
        #pragma unroll
        for (int u = 0; u < 4; u++) al[u] = a_s[r0 + u];
        #pragma unroll
        for (int u = 0; u < 4; u++)
            #pragma unroll
            for (int v = 0; v < 4; v++)
                o[u][v] *= al[u];
        #pragma unroll
        for (int j = 0; j < 64; j++) {
            float a[4], b[4];
            #pragma unroll
            for (int u = 0; u < 4; u++) a[u] = Ps[j * 65 + r0 + u];
            #pragma unroll
            for (int u = 0; u < 4; u++) b[u] = Vs[j * 64 + c0 + u];
            #pragma unroll
            for (int u = 0; u < 4; u++)
                #pragma unroll
                for (int v = 0; v < 4; v++)
                    o[u][v] = fmaf(a[u], b[v], o[u][v]);
        }
        __syncthreads();   // before next tile overwrites Ks/Vs/Ps
    }

    // epilogue: normalize and write ctx (concatenated heads, row-major [N, H*E])
    float inv[4];
    #pragma unroll
    for (int u = 0; u < 4; u++) inv[u] = 1.f / l_s[r0 + u];
    #pragma unroll
    for (int u = 0; u < 4; u++)
        #pragma unroll
        for (int v = 0; v < 4; v++)
            g_ctx[(size_t)(q0 + r0 + u) * D_IN + h * E + c0 + v] = o[u][v] * inv[u];
}

// ---------------------------------------------------------------------------
// Kernel 3: output projection. out = ctx[2048,1024] @ o_proj[1024,1024]
// grid = (32, 16); block = 256; 64x64 tile, BK = 32.
// ---------------------------------------------------------------------------
__global__ __launch_bounds__(256) void outproj_kernel(
    const float* __restrict__ Wo, float* __restrict__ out)
{
    __shared__ float As[32 * 65];
    __shared__ float Bs[32 * 64];

    const int tid = threadIdx.x;
    const int m0 = blockIdx.x * 64;
    const int n0 = blockIdx.y * 64;
    const int tr = tid >> 4, tc = tid & 15;
    const int r0 = tr * 4,   c0 = tc * 4;

    float acc[4][4] = {};

    for (int k0 = 0; k0 < D_IN; k0 += 32) {
        #pragma unroll
        for (int i = 0; i < 8; i++) {
            int idx = tid + i * 256;
            int r = idx >> 5, k = idx & 31;
            As[k * 65 + r] = g_ctx[(size_t)(m0 + r) * D_IN + k0 + k];
        }
        #pragma unroll
        for (int i = 0; i < 8; i++) {
            int idx = tid + i * 256;
            int k = idx >> 6, e = idx & 63;
            Bs[k * 64 + e] = Wo[(size_t)(k0 + k) * D_IN + n0 + e];
        }
        __syncthreads();

        #pragma unroll
        for (int k = 0; k < 32; k++) {
            float a[4], b[4];
            #pragma unroll
            for (int u = 0; u < 4; u++) a[u] = As[k * 65 + r0 + u];
            #pragma unroll
            for (int u = 0; u < 4; u++) b[u] = Bs[k * 64 + c0 + u];
            #pragma unroll
            for (int u = 0; u < 4; u++)
                #pragma unroll
                for (int v = 0; v < 4; v++)
                    acc[u][v] = fmaf(a[u], b[v], acc[u][v]);
        }
        __syncthreads();
    }

    #pragma unroll
    for (int u = 0; u < 4; u++)
        #pragma unroll
        for (int v = 0; v < 4; v++)
            out[(size_t)(m0 + r0 + u) * D_IN + n0 + c0 + v] = acc[u][v];
}

// ---------------------------------------------------------------------------
extern "C" void kernel_launch(void* const* d_in, const int* in_sizes, int n_in,
                              void* d_out, int out_size)
{
    const float* x  = (const float*)d_in[0];
    const float* Wq = (const float*)d_in[1];
    const float* Wk = (const float*)d_in[2];
    const float* Wv = (const float*)d_in[3];
    const float* Wo = (const float*)d_in[4];
    float* out = (float*)d_out;

    (void)in_sizes; (void)n_in; (void)out_size;

    const int attn_smem = ATTN_SMEM_FLOATS * (int)sizeof(float);  // ~68 KB
    cudaFuncSetAttribute(attn_kernel,
                         cudaFuncAttributeMaxDynamicSharedMemorySize, attn_smem);

    dim3 g1(N_TOK / 64, NH, 3);
    qkv_kernel<<<g1, 256>>>(x, Wq, Wk, Wv);

    dim3 g2(N_TOK / 64, NH);
    attn_kernel<<<g2, 256, attn_smem>>>();

    dim3 g3(N_TOK / 64, D_IN / 64);
    outproj_kernel<<<g3, 256>>>(Wo, out);
}

// round 2
// speedup vs baseline: 1.1290x; 1.1290x over previous
#include <cuda_runtime.h>
#include <math.h>

#define N_TOK 2048
#define D_IN  1024
#define NH    16
#define E     64

// Scratch (allocation-free: __device__ globals). Layout [h][n][e].
__device__ float g_Q[NH * N_TOK * E];
__device__ float g_K[NH * N_TOK * E];
__device__ float g_V[NH * N_TOK * E];
__device__ float g_ctx[N_TOK * D_IN];

// ---------------------------------------------------------------------------
// Kernel 1: fused QKV projection as one GEMM C[2048, 3072] = X @ [Wq|Wk|Wv].
// 128x128 block tile, BK=16, 256 threads, 8x8 per thread, double-buffered.
// grid = (3072/128 = 24, 2048/128 = 16)
// ---------------------------------------------------------------------------
__global__ __launch_bounds__(256, 2) void qkv_kernel(
    const float* __restrict__ x,
    const float* __restrict__ Wq,
    const float* __restrict__ Wk,
    const float* __restrict__ Wv)
{
    __shared__ __align__(16) float As[2][16 * 132];  // As[k][m], pad 132
    __shared__ __align__(16) float Bs[2][16 * 132];  // Bs[k][n], pad 132

    const int tid = threadIdx.x;
    const int n0  = blockIdx.x * 128;   // global col in [0, 3072)
    const int m0  = blockIdx.y * 128;

    const int sel = n0 >> 10;
    const float* W = (sel == 0 ? Wq : (sel == 1 ? Wk : Wv));
    float*     Out = (sel == 0 ? g_Q : (sel == 1 ? g_K : g_V));
    const int h0 = (n0 & 1023) >> 6;                 // tile spans heads h0, h0+1
    const float* Wb = W + (size_t)h0 * (D_IN * E);

    // loader mapping
    const int a_row = tid >> 2;            // 0..63  (rows, +64 for second half)
    const int a_k4  = (tid & 3) * 4;       // k offset 0..12
    const int b_k   = tid >> 5;            // 0..7   (+8 for second half)
    const int b_c4  = (tid & 31) * 4;      // col 0..124
    const int b_e   = b_c4 & 63;
    const int b_hh  = b_c4 >> 6;

    // compute mapping
    const int ty = tid >> 4, tx = tid & 15;
    const int r0 = ty * 4,   c0 = tx * 4;

    float acc[8][8] = {};

    // ---- load tile 0 into buffer 0
    {
        #pragma unroll
        for (int i = 0; i < 2; i++) {
            int row = a_row + i * 64;
            float4 v = *(const float4*)(x + (size_t)(m0 + row) * D_IN + a_k4);
            As[0][(a_k4 + 0) * 132 + row] = v.x;
            As[0][(a_k4 + 1) * 132 + row] = v.y;
            As[0][(a_k4 + 2) * 132 + row] = v.z;
            As[0][(a_k4 + 3) * 132 + row] = v.w;
        }
        #pragma unroll
        for (int i = 0; i < 2; i++) {
            int k = b_k + i * 8;
            float4 v = *(const float4*)(Wb + (size_t)b_hh * (D_IN * E) + (size_t)k * E + b_e);
            *(float4*)(&Bs[0][k * 132 + b_c4]) = v;
        }
    }
    __syncthreads();

    float4 pa0, pa1, pb0, pb1;
    const int NT = D_IN / 16;
    for (int t = 0; t < NT; t++) {
        const int cur = t & 1;
        if (t + 1 < NT) {
            const int k0 = (t + 1) * 16;
            pa0 = *(const float4*)(x + (size_t)(m0 + a_row)      * D_IN + k0 + a_k4);
            pa1 = *(const float4*)(x + (size_t)(m0 + a_row + 64) * D_IN + k0 + a_k4);
            pb0 = *(const float4*)(Wb + (size_t)b_hh * (D_IN * E) + (size_t)(k0 + b_k)     * E + b_e);
            pb1 = *(const float4*)(Wb + (size_t)b_hh * (D_IN * E) + (size_t)(k0 + b_k + 8) * E + b_e);
        }
        const float* Ab = As[cur];
        const float* Bb = Bs[cur];
        #pragma unroll
        for (int k = 0; k < 16; k++) {
            float4 a0 = *(const float4*)(Ab + k * 132 + r0);
            float4 a1 = *(const float4*)(Ab + k * 132 + 64 + r0);
            float4 b0 = *(const float4*)(Bb + k * 132 + c0);
            float4 b1 = *(const float4*)(Bb + k * 132 + 64 + c0);
            float av[8] = {a0.x,a0.y,a0.z,a0.w,a1.x,a1.y,a1.z,a1.w};
            float bv[8] = {b0.x,b0.y,b0.z,b0.w,b1.x,b1.y,b1.z,b1.w};
            #pragma unroll
            for (int u = 0; u < 8; u++)
                #pragma unroll
                for (int v = 0; v < 8; v++)
                    acc[u][v] = fmaf(av[u], bv[v], acc[u][v]);
        }
        if (t + 1 < NT) {
            const int nb = 1 - cur;
            As[nb][(a_k4 + 0) * 132 + a_row] = pa0.x;
            As[nb][(a_k4 + 1) * 132 + a_row] = pa0.y;
            As[nb][(a_k4 + 2) * 132 + a_row] = pa0.z;
            As[nb][(a_k4 + 3) * 132 + a_row] = pa0.w;
            As[nb][(a_k4 + 0) * 132 + a_row + 64] = pa1.x;
            As[nb][(a_k4 + 1) * 132 + a_row + 64] = pa1.y;
            As[nb][(a_k4 + 2) * 132 + a_row + 64] = pa1.z;
            As[nb][(a_k4 + 3) * 132 + a_row + 64] = pa1.w;
            *(float4*)(&Bs[nb][b_k * 132 + b_c4])       = pb0;
            *(float4*)(&Bs[nb][(b_k + 8) * 132 + b_c4]) = pb1;
        }
        __syncthreads();
    }

    // epilogue: scatter to per-head layout [h][n][e]
    #pragma unroll
    for (int u = 0; u < 8; u++) {
        int row = m0 + (u < 4 ? r0 + u : 64 + r0 + u - 4);
        #pragma unroll
        for (int q = 0; q < 2; q++) {
            float4 v = make_float4(acc[u][q*4+0], acc[u][q*4+1], acc[u][q*4+2], acc[u][q*4+3]);
            *(float4*)(Out + (((size_t)(h0 + q)) * N_TOK + row) * E + c0) = v;
        }
    }
}

// ---------------------------------------------------------------------------
// Kernel 2: flash attention per head. BQ = BK = 64, d = 64, online softmax.
// grid = (32 q-tiles, 16 heads); block = 256 threads; float4 smem (pad 68).
// ---------------------------------------------------------------------------
#define ATTN_SMEM_FLOATS (4 * 64 * 68 + 64 * 3 + 256)

__global__ __launch_bounds__(256) void attn_kernel()
{
    extern __shared__ __align__(16) float sm[];
    float* Qs  = sm;                 // Qst[e][i]  [64][68]
    float* Ks  = Qs + 64 * 68;       // Kst[e][j]  [64][68]
    float* Vs  = Ks + 64 * 68;       // Vs[j][e]   [64][68]
    float* Ps  = Vs + 64 * 68;       // Pst[j][i]  [64][68]
    float* m_s = Ps + 64 * 68;       // [64]
    float* l_s = m_s + 64;
    float* a_s = l_s + 64;
    float* red = a_s + 64;           // [4][64]

    const int tid = threadIdx.x;
    const int h   = blockIdx.y;
    const int q0  = blockIdx.x * 64;
    const int tr  = tid >> 4, tc = tid & 15;
    const int r0  = tr * 4,   c0 = tc * 4;
    const float scale = 0.125f;      // 1/sqrt(64)

    const int l_row = tid >> 4;           // 0..15 (+16,32,48)
    const int l_e4  = (tid & 15) * 4;

    // load Q tile (transposed to [e][i])
    {
        const float* Qg = g_Q + ((size_t)h * N_TOK + q0) * E;
        #pragma unroll
        for (int i = 0; i < 4; i++) {
            int row = l_row + i * 16;
            float4 v = *(const float4*)(Qg + (size_t)row * E + l_e4);
            Qs[(l_e4 + 0) * 68 + row] = v.x;
            Qs[(l_e4 + 1) * 68 + row] = v.y;
            Qs[(l_e4 + 2) * 68 + row] = v.z;
            Qs[(l_e4 + 3) * 68 + row] = v.w;
        }
    }
    if (tid < 64) { m_s[tid] = -INFINITY; l_s[tid] = 0.f; }

    float o[4][4] = {};
    __syncthreads();

    for (int kt = 0; kt < N_TOK; kt += 64) {
        const float* Kg = g_K + ((size_t)h * N_TOK + kt) * E;
        const float* Vg = g_V + ((size_t)h * N_TOK + kt) * E;
        #pragma unroll
        for (int i = 0; i < 4; i++) {
            int row = l_row + i * 16;
            float4 kv = *(const float4*)(Kg + (size_t)row * E + l_e4);
            Ks[(l_e4 + 0) * 68 + row] = kv.x;
            Ks[(l_e4 + 1) * 68 + row] = kv.y;
            Ks[(l_e4 + 2) * 68 + row] = kv.z;
            Ks[(l_e4 + 3) * 68 + row] = kv.w;
            float4 vv = *(const float4*)(Vg + (size_t)row * E + l_e4);
            *(float4*)(Vs + row * 68 + l_e4) = vv;
        }
        __syncthreads();

        // S = Q K^T  (4x4 per thread)
        float s[4][4] = {};
        #pragma unroll 4
        for (int e = 0; e < 64; e++) {
            float4 a = *(const float4*)(Qs + e * 68 + r0);
            float4 b = *(const float4*)(Ks + e * 68 + c0);
            float av[4] = {a.x,a.y,a.z,a.w};
            float bv[4] = {b.x,b.y,b.z,b.w};
            #pragma unroll
            for (int u = 0; u < 4; u++)
                #pragma unroll
                for (int v = 0; v < 4; v++)
                    s[u][v] = fmaf(av[u], bv[v], s[u][v]);
        }
        // stage S (scaled) transposed: Ps[j][i]
        #pragma unroll
        for (int u = 0; u < 4; u++)
            #pragma unroll
            for (int v = 0; v < 4; v++)
                Ps[(c0 + v) * 68 + (r0 + u)] = s[u][v] * scale;
        __syncthreads();

        // per-row max
        {
            int i = tid & 63, qd = tid >> 6;
            float pm = -INFINITY;
            #pragma unroll
            for (int j = 0; j < 16; j++)
                pm = fmaxf(pm, Ps[(qd * 16 + j) * 68 + i]);
            red[qd * 64 + i] = pm;
        }
        __syncthreads();
        if (tid < 64) {
            float mt = fmaxf(fmaxf(red[tid], red[64 + tid]),
                             fmaxf(red[128 + tid], red[192 + tid]));
            float mo = m_s[tid];
            float mn = fmaxf(mo, mt);
            a_s[tid] = __expf(mo - mn);
            m_s[tid] = mn;
        }
        __syncthreads();
        // exponentiate + partial row sums
        {
            int i = tid & 63, qd = tid >> 6;
            float mi = m_s[i];
            float ps = 0.f;
            #pragma unroll
            for (int j = 0; j < 16; j++) {
                float* p = &Ps[(qd * 16 + j) * 68 + i];
                float v = __expf(*p - mi);
                *p = v; ps += v;
            }
            red[qd * 64 + i] = ps;
        }
        __syncthreads();
        if (tid < 64) {
            float rs = red[tid] + red[64 + tid] + red[128 + tid] + red[192 + tid];
            l_s[tid] = l_s[tid] * a_s[tid] + rs;
        }

        // O = O*alpha + P @ V
        float al[4];
        #pragma unroll
        for (int u = 0; u < 4; u++) al[u] = a_s[r0 + u];
        #pragma unroll
        for (int u = 0; u < 4; u++)
            #pragma unroll
            for (int v = 0; v < 4; v++)
                o[u][v] *= al[u];
        #pragma unroll 4
        for (int j = 0; j < 64; j++) {
            float4 a = *(const float4*)(Ps + j * 68 + r0);
            float4 b = *(const float4*)(Vs + j * 68 + c0);
            float av[4] = {a.x,a.y,a.z,a.w};
            float bv[4] = {b.x,b.y,b.z,b.w};
            #pragma unroll
            for (int u = 0; u < 4; u++)
                #pragma unroll
                for (int v = 0; v < 4; v++)
                    o[u][v] = fmaf(av[u], bv[v], o[u][v]);
        }
        __syncthreads();   // before next tile overwrites Ks/Vs/Ps
    }

    // epilogue: normalize and write ctx [n][h*E]
    float inv[4];
    #pragma unroll
    for (int u = 0; u < 4; u++) inv[u] = 1.f / l_s[r0 + u];
    #pragma unroll
    for (int u = 0; u < 4; u++) {
        float4 v = make_float4(o[u][0] * inv[u], o[u][1] * inv[u],
                               o[u][2] * inv[u], o[u][3] * inv[u]);
        *(float4*)(g_ctx + (size_t)(q0 + r0 + u) * D_IN + h * E + c0) = v;
    }
}

// ---------------------------------------------------------------------------
// Kernel 3: output projection. out[2048,1024] = ctx @ Wo.
// 128x64 block tile, BK=16, 256 threads, 8x4 per thread, double-buffered.
// grid = (1024/64 = 16, 2048/128 = 16)
// ---------------------------------------------------------------------------
__global__ __launch_bounds__(256, 2) void outproj_kernel(
    const float* __restrict__ Wo, float* __restrict__ out)
{
    __shared__ __align__(16) float As[2][16 * 132];
    __shared__ __align__(16) float Bs[2][16 * 68];

    const int tid = threadIdx.x;
    const int n0  = blockIdx.x * 64;
    const int m0  = blockIdx.y * 128;

    const int a_row = tid >> 2;
    const int a_k4  = (tid & 3) * 4;
    const int b_k   = tid >> 4;            // 0..15
    const int b_c4  = (tid & 15) * 4;      // 0..60

    const int ty = tid >> 4, tx = tid & 15;
    const int r0 = ty * 4,   c0 = tx * 4;

    float acc[8][4] = {};

    {
        #pragma unroll
        for (int i = 0; i < 2; i++) {
            int row = a_row + i * 64;
            float4 v = *(const float4*)(g_ctx + (size_t)(m0 + row) * D_IN + a_k4);
            As[0][(a_k4 + 0) * 132 + row] = v.x;
            As[0][(a_k4 + 1) * 132 + row] = v.y;
            As[0][(a_k4 + 2) * 132 + row] = v.z;
            As[0][(a_k4 + 3) * 132 + row] = v.w;
        }
        float4 v = *(const float4*)(Wo + (size_t)b_k * D_IN + n0 + b_c4);
        *(float4*)(&Bs[0][b_k * 68 + b_c4]) = v;
    }
    __syncthreads();

    float4 pa0, pa1, pb0;
    const int NT = D_IN / 16;
    for (int t = 0; t < NT; t++) {
        const int cur = t & 1;
        if (t + 1 < NT) {
            const int k0 = (t + 1) * 16;
            pa0 = *(const float4*)(g_ctx + (size_t)(m0 + a_row)      * D_IN + k0 + a_k4);
            pa1 = *(const float4*)(g_ctx + (size_t)(m0 + a_row + 64) * D_IN + k0 + a_k4);
            pb0 = *(const float4*)(Wo + (size_t)(k0 + b_k) * D_IN + n0 + b_c4);
        }
        const float* Ab = As[cur];
        const float* Bb = Bs[cur];
        #pragma unroll
        for (int k = 0; k < 16; k++) {
            float4 a0 = *(const float4*)(Ab + k * 132 + r0);
            float4 a1 = *(const float4*)(Ab + k * 132 + 64 + r0);
            float4 b0 = *(const float4*)(Bb + k * 68 + c0);
            float av[8] = {a0.x,a0.y,a0.z,a0.w,a1.x,a1.y,a1.z,a1.w};
            float bv[4] = {b0.x,b0.y,b0.z,b0.w};
            #pragma unroll
            for (int u = 0; u < 8; u++)
                #pragma unroll
                for (int v = 0; v < 4; v++)
                    acc[u][v] = fmaf(av[u], bv[v], acc[u][v]);
        }
        if (t + 1 < NT) {
            const int nb = 1 - cur;
            As[nb][(a_k4 + 0) * 132 + a_row] = pa0.x;
            As[nb][(a_k4 + 1) * 132 + a_row] = pa0.y;
            As[nb][(a_k4 + 2) * 132 + a_row] = pa0.z;
            As[nb][(a_k4 + 3) * 132 + a_row] = pa0.w;
            As[nb][(a_k4 + 0) * 132 + a_row + 64] = pa1.x;
            As[nb][(a_k4 + 1) * 132 + a_row + 64] = pa1.y;
            As[nb][(a_k4 + 2) * 132 + a_row + 64] = pa1.z;
            As[nb][(a_k4 + 3) * 132 + a_row + 64] = pa1.w;
            *(float4*)(&Bs[nb][b_k * 68 + b_c4]) = pb0;
        }
        __syncthreads();
    }

    #pragma unroll
    for (int u = 0; u < 8; u++) {
        int row = m0 + (u < 4 ? r0 + u : 64 + r0 + u - 4);
        float4 v = make_float4(acc[u][0], acc[u][1], acc[u][2], acc[u][3]);
        *(float4*)(out + (size_t)row * D_IN + n0 + c0) = v;
    }
}

// ---------------------------------------------------------------------------
extern "C" void kernel_launch(void* const* d_in, const int* in_sizes, int n_in,
                              void* d_out, int out_size)
{
    const float* x  = (const float*)d_in[0];
    const float* Wq = (const float*)d_in[1];
    const float* Wk = (const float*)d_in[2];
    const float* Wv = (const float*)d_in[3];
    const float* Wo = (const float*)d_in[4];
    float* out = (float*)d_out;

    (void)in_sizes; (void)n_in; (void)out_size;

    const int attn_smem = ATTN_SMEM_FLOATS * (int)sizeof(float);
    cudaFuncSetAttribute(attn_kernel,
                         cudaFuncAttributeMaxDynamicSharedMemorySize, attn_smem);

    dim3 g1(3072 / 128, N_TOK / 128);
    qkv_kernel<<<g1, 256>>>(x, Wq, Wk, Wv);

    dim3 g2(N_TOK / 64, NH);
    attn_kernel<<<g2, 256, attn_smem>>>();

    dim3 g3(D_IN / 64, N_TOK / 128);
    outproj_kernel<<<g3, 256>>>(Wo, out);
}

// round 4
// speedup vs baseline: 1.3593x; 1.2040x over previous
#include <cuda_runtime.h>
#include <cuda_bf16.h>
#include <math.h>
#include <stdint.h>

#define N_TOK 2048
#define D_IN  1024
#define NH    16
#define E     64

// ===========================================================================
// Device scratch
// ===========================================================================
__device__ float g_Q[NH * N_TOK * E];
__device__ float g_K[NH * N_TOK * E];
__device__ float g_V[NH * N_TOK * E];

__device__ __nv_bfloat16 g_xh[N_TOK * D_IN];
__device__ __nv_bfloat16 g_xl[N_TOK * D_IN];
__device__ __nv_bfloat16 g_Wth[3072 * D_IN];   // [n][k], n = sel*1024 + h*64 + e
__device__ __nv_bfloat16 g_Wtl[3072 * D_IN];
__device__ __nv_bfloat16 g_Woth[D_IN * D_IN];  // [n][k] = Wo[k][n]
__device__ __nv_bfloat16 g_Wotl[D_IN * D_IN];
__device__ __nv_bfloat16 g_ctxh[N_TOK * D_IN];
__device__ __nv_bfloat16 g_ctxl[N_TOK * D_IN];

__device__ __forceinline__ void split_store(float v, __nv_bfloat16* hi, __nv_bfloat16* lo) {
    __nv_bfloat16 h = __float2bfloat16(v);
    *hi = h;
    *lo = __float2bfloat16(v - __bfloat162float(h));
}

__device__ __forceinline__ uint32_t smem_u32(const void* p) {
    uint32_t a;
    asm("{ .reg .u64 t; cvta.to.shared.u64 t, %1; cvt.u32.u64 %0, t; }" : "=r"(a) : "l"(p));
    return a;
}
__device__ __forceinline__ void cp16(uint32_t dst, const void* src) {
    asm volatile("cp.async.cg.shared.global [%0], [%1], 16;" :: "r"(dst), "l"(src) : "memory");
}
#define CP_COMMIT() asm volatile("cp.async.commit_group;" ::: "memory")

__device__ __forceinline__ void mma_bf16(float* d, const uint32_t* a, const uint32_t* b) {
    asm volatile(
        "mma.sync.aligned.m16n8k16.row.col.f32.bf16.bf16.f32 "
        "{%0,%1,%2,%3}, {%4,%5,%6,%7}, {%8,%9}, {%0,%1,%2,%3};"
        : "+f"(d[0]), "+f"(d[1]), "+f"(d[2]), "+f"(d[3])
        : "r"(a[0]), "r"(a[1]), "r"(a[2]), "r"(a[3]), "r"(b[0]), "r"(b[1]));
}

// ===========================================================================
// Prep kernels
// ===========================================================================
__global__ __launch_bounds__(256) void split_x_kernel(const float* __restrict__ x)
{
    int i0 = (blockIdx.x * 256 + threadIdx.x) * 4;
    float4 v = *(const float4*)(x + i0);
    split_store(v.x, &g_xh[i0 + 0], &g_xl[i0 + 0]);
    split_store(v.y, &g_xh[i0 + 1], &g_xl[i0 + 1]);
    split_store(v.z, &g_xh[i0 + 2], &g_xl[i0 + 2]);
    split_store(v.w, &g_xh[i0 + 3], &g_xl[i0 + 3]);
}

__global__ __launch_bounds__(256) void conv_w_kernel(
    const float* __restrict__ Wq, const float* __restrict__ Wk, const float* __restrict__ Wv)
{
    int idx = blockIdx.x * 256 + threadIdx.x;   // n*256 + d-block
    int n  = idx >> 8;
    int d0 = (idx & 255) << 2;
    int sel = n >> 10, w = n & 1023, h = w >> 6, e = w & 63;
    const float* W = (sel == 0 ? Wq : (sel == 1 ? Wk : Wv));
    const float* p = W + (size_t)h * (D_IN * E) + e;
    #pragma unroll
    for (int i = 0; i < 4; i++) {
        float v = p[(size_t)(d0 + i) * E];
        split_store(v, &g_Wth[(size_t)n * D_IN + d0 + i], &g_Wtl[(size_t)n * D_IN + d0 + i]);
    }
}

__global__ __launch_bounds__(256) void conv_wo_kernel(const float* __restrict__ Wo)
{
    int idx = blockIdx.x * 256 + threadIdx.x;
    int n  = idx >> 8;
    int k0 = (idx & 255) << 2;
    #pragma unroll
    for (int i = 0; i < 4; i++) {
        float v = Wo[(size_t)(k0 + i) * D_IN + n];
        split_store(v, &g_Woth[(size_t)n * D_IN + k0 + i], &g_Wotl[(size_t)n * D_IN + k0 + i]);
    }
}

// ===========================================================================
// Split-bf16 GEMM on mma.sync (HMMA): C[M,N] = A[M,K] @ B[N,K]^T, fp32 out.
// CTA: 128x128 tile, 256 thr (8 warps, warp tile 32x64), BK=32, cp.async x2.
// Smem tile layout: [row][k] bf16, row stride 40 (80B: 16B-aligned, LDS
// fragment reads conflict-free). Tiles: Ah, Al, Bh, Bl.
// mode 0: scatter into g_Q/g_K/g_V per-head; mode 1: dense out [2048,1024].
// ===========================================================================
#define TSTRIDE 40
#define TILE_E  (128 * TSTRIDE)          // elems per tile
#define BUF_E   (4 * TILE_E)             // elems per buffer
#define GEMM_SMEM (2 * BUF_E * 2)        // bytes (bf16), = 81920

__global__ __launch_bounds__(256) void gemm_kernel(
    const __nv_bfloat16* __restrict__ Ah, const __nv_bfloat16* __restrict__ Al,
    const __nv_bfloat16* __restrict__ Bh, const __nv_bfloat16* __restrict__ Bl,
    int mode, float* __restrict__ outp)
{
    extern __shared__ __align__(16) __nv_bfloat16 sm[];
    const int tid  = threadIdx.x;
    const int wid  = tid >> 5, lane = tid & 31;
    const int grp  = lane >> 2, qid = lane & 3;
    const int n0   = blockIdx.x * 128, m0 = blockIdx.y * 128;
    const int wm   = (wid >> 1) * 32;        // warp M offset
    const int wn   = (wid & 1) * 64;         // warp N offset

    // loader mapping: rows r0,r1; 8-elem column chunk
    const int lr0 = tid >> 2;
    const int lc8 = (tid & 3) * 8;
    const __nv_bfloat16* srcs[4] = {Ah, Al, Bh, Bl};

    const uint32_t smb = smem_u32(sm);

    float acc[2][8][4] = {};

    // ---- issue chunk 0
    #pragma unroll
    for (int t = 0; t < 4; t++) {
        const __nv_bfloat16* S = srcs[t] + (size_t)((t < 2 ? m0 : n0)) * D_IN + lc8;
        uint32_t dst = smb + (t * TILE_E) * 2 + lc8 * 2;
        cp16(dst + lr0 * (TSTRIDE * 2),        S + (size_t)lr0 * D_IN);
        cp16(dst + (lr0 + 64) * (TSTRIDE * 2), S + (size_t)(lr0 + 64) * D_IN);
    }
    CP_COMMIT();

    const int NC = D_IN / 32;
    for (int kc = 0; kc < NC; kc++) {
        const int cur = kc & 1;
        if (kc + 1 < NC) {
            const int nb = 1 - cur;
            #pragma unroll
            for (int t = 0; t < 4; t++) {
                const __nv_bfloat16* S = srcs[t] + (size_t)((t < 2 ? m0 : n0)) * D_IN
                                         + (kc + 1) * 32 + lc8;
                uint32_t dst = smb + (nb * BUF_E + t * TILE_E) * 2 + lc8 * 2;
                cp16(dst + lr0 * (TSTRIDE * 2),        S + (size_t)lr0 * D_IN);
                cp16(dst + (lr0 + 64) * (TSTRIDE * 2), S + (size_t)(lr0 + 64) * D_IN);
            }
            CP_COMMIT();
            asm volatile("cp.async.wait_group 1;" ::: "memory");
        } else {
            asm volatile("cp.async.wait_group 0;" ::: "memory");
        }
        __syncthreads();

        const __nv_bfloat16* Asm_h = sm + cur * BUF_E;
        const __nv_bfloat16* Asm_l = Asm_h + TILE_E;
        const __nv_bfloat16* Bsm_h = Asm_h + 2 * TILE_E;
        const __nv_bfloat16* Bsm_l = Asm_h + 3 * TILE_E;

        #pragma unroll
        for (int k16 = 0; k16 < 32; k16 += 16) {
            // A fragments for 2 m16 tiles, hi and lo
            uint32_t ah[2][4], al[2][4];
            #pragma unroll
            for (int mt = 0; mt < 2; mt++) {
                int r = wm + mt * 16 + grp;
                int c = k16 + qid * 2;
                ah[mt][0] = *(const uint32_t*)(Asm_h + r * TSTRIDE + c);
                ah[mt][1] = *(const uint32_t*)(Asm_h + (r + 8) * TSTRIDE + c);
                ah[mt][2] = *(const uint32_t*)(Asm_h + r * TSTRIDE + c + 8);
                ah[mt][3] = *(const uint32_t*)(Asm_h + (r + 8) * TSTRIDE + c + 8);
                al[mt][0] = *(const uint32_t*)(Asm_l + r * TSTRIDE + c);
                al[mt][1] = *(const uint32_t*)(Asm_l + (r + 8) * TSTRIDE + c);
                al[mt][2] = *(const uint32_t*)(Asm_l + r * TSTRIDE + c + 8);
                al[mt][3] = *(const uint32_t*)(Asm_l + (r + 8) * TSTRIDE + c + 8);
            }
            #pragma unroll
            for (int nt = 0; nt < 8; nt++) {
                int nr = wn + nt * 8 + grp;
                int c  = k16 + qid * 2;
                uint32_t bh[2], bl[2];
                bh[0] = *(const uint32_t*)(Bsm_h + nr * TSTRIDE + c);
                bh[1] = *(const uint32_t*)(Bsm_h + nr * TSTRIDE + c + 8);
                bl[0] = *(const uint32_t*)(Bsm_l + nr * TSTRIDE + c);
                bl[1] = *(const uint32_t*)(Bsm_l + nr * TSTRIDE + c + 8);
                #pragma unroll
                for (int mt = 0; mt < 2; mt++) {
                    mma_bf16(acc[mt][nt], ah[mt], bh);
                    mma_bf16(acc[mt][nt], ah[mt], bl);
                    mma_bf16(acc[mt][nt], al[mt], bh);
                }
            }
        }
        __syncthreads();
    }

    // ---- epilogue
    #pragma unroll
    for (int mt = 0; mt < 2; mt++) {
        #pragma unroll
        for (int nt = 0; nt < 8; nt++) {
            int n = n0 + wn + nt * 8 + qid * 2;
            #pragma unroll
            for (int half = 0; half < 2; half++) {
                int m = m0 + wm + mt * 16 + grp + half * 8;
                float2 v = make_float2(acc[mt][nt][half * 2], acc[mt][nt][half * 2 + 1]);
                if (mode == 0) {
                    int sel = n >> 10, w = n & 1023, h = w >> 6, e = w & 63;
                    float* base = (sel == 0 ? g_Q : (sel == 1 ? g_K : g_V));
                    *(float2*)(base + ((size_t)h * N_TOK + m) * E + e) = v;
                } else {
                    *(float2*)(outp + (size_t)m * D_IN + n) = v;
                }
            }
        }
    }
}

// ===========================================================================
// Kernel 2: flash attention per head (SIMT fp32). Epilogue -> split bf16 ctx.
// ===========================================================================
#define ATTN_SMEM_FLOATS (4 * 64 * 68 + 64 * 3 + 256)

__global__ __launch_bounds__(256) void attn_kernel()
{
    extern __shared__ __align__(16) float smf[];
    float* Qs  = smf;
    float* Ks  = Qs + 64 * 68;
    float* Vs  = Ks + 64 * 68;
    float* Ps  = Vs + 64 * 68;
    float* m_s = Ps + 64 * 68;
    float* l_s = m_s + 64;
    float* a_s = l_s + 64;
    float* red = a_s + 64;

    const int tid = threadIdx.x;
    const int h   = blockIdx.y;
    const int q0  = blockIdx.x * 64;
    const int tr  = tid >> 4, tc = tid & 15;
    const int r0  = tr * 4,   c0 = tc * 4;
    const float scale = 0.125f;

    const int l_row = tid >> 4;
    const int l_e4  = (tid & 15) * 4;

    {
        const float* Qg = g_Q + ((size_t)h * N_TOK + q0) * E;
        #pragma unroll
        for (int i = 0; i < 4; i++) {
            int row = l_row + i * 16;
            float4 v = *(const float4*)(Qg + (size_t)row * E + l_e4);
            Qs[(l_e4 + 0) * 68 + row] = v.x;
            Qs[(l_e4 + 1) * 68 + row] = v.y;
            Qs[(l_e4 + 2) * 68 + row] = v.z;
            Qs[(l_e4 + 3) * 68 + row] = v.w;
        }
    }
    if (tid < 64) { m_s[tid] = -INFINITY; l_s[tid] = 0.f; }

    float o[4][4] = {};
    __syncthreads();

    for (int kt = 0; kt < N_TOK; kt += 64) {
        const float* Kg = g_K + ((size_t)h * N_TOK + kt) * E;
        const float* Vg = g_V + ((size_t)h * N_TOK + kt) * E;
        #pragma unroll
        for (int i = 0; i < 4; i++) {
            int row = l_row + i * 16;
            float4 kv = *(const float4*)(Kg + (size_t)row * E + l_e4);
            Ks[(l_e4 + 0) * 68 + row] = kv.x;
            Ks[(l_e4 + 1) * 68 + row] = kv.y;
            Ks[(l_e4 + 2) * 68 + row] = kv.z;
            Ks[(l_e4 + 3) * 68 + row] = kv.w;
            float4 vv = *(const float4*)(Vg + (size_t)row * E + l_e4);
            *(float4*)(Vs + row * 68 + l_e4) = vv;
        }
        __syncthreads();

        float s[4][4] = {};
        #pragma unroll 4
        for (int e = 0; e < 64; e++) {
            float4 a = *(const float4*)(Qs + e * 68 + r0);
            float4 b = *(const float4*)(Ks + e * 68 + c0);
            float av[4] = {a.x, a.y, a.z, a.w};
            float bv[4] = {b.x, b.y, b.z, b.w};
            #pragma unroll
            for (int u = 0; u < 4; u++)
                #pragma unroll
                for (int v = 0; v < 4; v++)
                    s[u][v] = fmaf(av[u], bv[v], s[u][v]);
        }
        #pragma unroll
        for (int u = 0; u < 4; u++)
            #pragma unroll
            for (int v = 0; v < 4; v++)
                Ps[(c0 + v) * 68 + (r0 + u)] = s[u][v] * scale;
        __syncthreads();

        {
            int i = tid & 63, qd = tid >> 6;
            float pm = -INFINITY;
            #pragma unroll
            for (int j = 0; j < 16; j++)
                pm = fmaxf(pm, Ps[(qd * 16 + j) * 68 + i]);
            red[qd * 64 + i] = pm;
        }
        __syncthreads();
        if (tid < 64) {
            float mt = fmaxf(fmaxf(red[tid], red[64 + tid]),
                             fmaxf(red[128 + tid], red[192 + tid]));
            float mo = m_s[tid];
            float mn = fmaxf(mo, mt);
            a_s[tid] = __expf(mo - mn);
            m_s[tid] = mn;
        }
        __syncthreads();
        {
            int i = tid & 63, qd = tid >> 6;
            float mi = m_s[i];
            float ps = 0.f;
            #pragma unroll
            for (int j = 0; j < 16; j++) {
                float* p = &Ps[(qd * 16 + j) * 68 + i];
                float v = __expf(*p - mi);
                *p = v; ps += v;
            }
            red[qd * 64 + i] = ps;
        }
        __syncthreads();
        if (tid < 64) {
            float rs = red[tid] + red[64 + tid] + red[128 + tid] + red[192 + tid];
            l_s[tid] = l_s[tid] * a_s[tid] + rs;
        }

        float al[4];
        #pragma unroll
        for (int u = 0; u < 4; u++) al[u] = a_s[r0 + u];
        #pragma unroll
        for (int u = 0; u < 4; u++)
            #pragma unroll
            for (int v = 0; v < 4; v++)
                o[u][v] *= al[u];
        #pragma unroll 4
        for (int j = 0; j < 64; j++) {
            float4 a = *(const float4*)(Ps + j * 68 + r0);
            float4 b = *(const float4*)(Vs + j * 68 + c0);
            float av[4] = {a.x, a.y, a.z, a.w};
            float bv[4] = {b.x, b.y, b.z, b.w};
            #pragma unroll
            for (int u = 0; u < 4; u++)
                #pragma unroll
                for (int v = 0; v < 4; v++)
                    o[u][v] = fmaf(av[u], bv[v], o[u][v]);
        }
        __syncthreads();
    }

    float inv[4];
    #pragma unroll
    for (int u = 0; u < 4; u++) inv[u] = 1.f / l_s[r0 + u];
    #pragma unroll
    for (int u = 0; u < 4; u++) {
        size_t base = (size_t)(q0 + r0 + u) * D_IN + h * E + c0;
        #pragma unroll
        for (int v = 0; v < 4; v++) {
            float f = o[u][v] * inv[u];
            split_store(f, &g_ctxh[base + v], &g_ctxl[base + v]);
        }
    }
}

// ===========================================================================
extern "C" void kernel_launch(void* const* d_in, const int* in_sizes, int n_in,
                              void* d_out, int out_size)
{
    const float* x  = (const float*)d_in[0];
    const float* Wq = (const float*)d_in[1];
    const float* Wk = (const float*)d_in[2];
    const float* Wv = (const float*)d_in[3];
    const float* Wo = (const float*)d_in[4];
    float* out = (float*)d_out;
    (void)in_sizes; (void)n_in; (void)out_size;

    const int attn_smem = ATTN_SMEM_FLOATS * (int)sizeof(float);
    cudaFuncSetAttribute(attn_kernel,
                         cudaFuncAttributeMaxDynamicSharedMemorySize, attn_smem);
    cudaFuncSetAttribute(gemm_kernel,
                         cudaFuncAttributeMaxDynamicSharedMemorySize, GEMM_SMEM);

    static __nv_bfloat16 *p_xh = nullptr, *p_xl, *p_Wth, *p_Wtl, *p_Woth, *p_Wotl, *p_ch, *p_cl;
    if (!p_xh) {
        cudaGetSymbolAddress((void**)&p_xh,  g_xh);
        cudaGetSymbolAddress((void**)&p_xl,  g_xl);
        cudaGetSymbolAddress((void**)&p_Wth, g_Wth);
        cudaGetSymbolAddress((void**)&p_Wtl, g_Wtl);
        cudaGetSymbolAddress((void**)&p_Woth, g_Woth);
        cudaGetSymbolAddress((void**)&p_Wotl, g_Wotl);
        cudaGetSymbolAddress((void**)&p_ch,  g_ctxh);
        cudaGetSymbolAddress((void**)&p_cl,  g_ctxl);
    }

    // prep: splits + weight transposes
    split_x_kernel<<<(N_TOK * D_IN) / (256 * 4), 256>>>(x);
    conv_w_kernel<<<3072, 256>>>(Wq, Wk, Wv);
    conv_wo_kernel<<<1024, 256>>>(Wo);

    // QKV: C[2048, 3072] = X @ Wcat^T -> g_Q/g_K/g_V
    dim3 g1(3072 / 128, N_TOK / 128);
    gemm_kernel<<<g1, 256, GEMM_SMEM>>>(p_xh, p_xl, p_Wth, p_Wtl, 0, nullptr);

    // attention
    dim3 g2(N_TOK / 64, NH);
    attn_kernel<<<g2, 256, attn_smem>>>();

    // out = ctx @ Wo : C[2048, 1024]
    dim3 g3(D_IN / 128, N_TOK / 128);
    gemm_kernel<<<g3, 256, GEMM_SMEM>>>(p_ch, p_cl, p_Woth, p_Wotl, 1, out);
}

// round 5
// speedup vs baseline: 2.4034x; 1.7681x over previous
#include <cuda_runtime.h>
#include <cuda_bf16.h>
#include <math.h>
#include <stdint.h>

#define N_TOK 2048
#define D_IN  1024
#define NH    16
#define E     64

// ===========================================================================
// Device scratch (split bf16 hi/lo everywhere)
// ===========================================================================
__device__ __nv_bfloat16 g_Qh[NH * N_TOK * E];
__device__ __nv_bfloat16 g_Ql[NH * N_TOK * E];
__device__ __nv_bfloat16 g_Kh[NH * N_TOK * E];
__device__ __nv_bfloat16 g_Kl[NH * N_TOK * E];
__device__ __nv_bfloat16 g_Vh[NH * N_TOK * E];
__device__ __nv_bfloat16 g_Vl[NH * N_TOK * E];

__device__ __nv_bfloat16 g_xh[N_TOK * D_IN];
__device__ __nv_bfloat16 g_xl[N_TOK * D_IN];
__device__ __nv_bfloat16 g_Wth[3072 * D_IN];   // [n][k], n = sel*1024 + h*64 + e
__device__ __nv_bfloat16 g_Wtl[3072 * D_IN];
__device__ __nv_bfloat16 g_Woth[D_IN * D_IN];  // [n][k] = Wo[k][n]
__device__ __nv_bfloat16 g_Wotl[D_IN * D_IN];
__device__ __nv_bfloat16 g_ctxh[N_TOK * D_IN];
__device__ __nv_bfloat16 g_ctxl[N_TOK * D_IN];

__device__ __forceinline__ void split_store(float v, __nv_bfloat16* hi, __nv_bfloat16* lo) {
    __nv_bfloat16 h = __float2bfloat16(v);
    *hi = h;
    *lo = __float2bfloat16(v - __bfloat162float(h));
}

__device__ __forceinline__ uint32_t smem_u32(const void* p) {
    uint32_t a;
    asm("{ .reg .u64 t; cvta.to.shared.u64 t, %1; cvt.u32.u64 %0, t; }" : "=r"(a) : "l"(p));
    return a;
}
__device__ __forceinline__ void cp16(uint32_t dst, const void* src) {
    asm volatile("cp.async.cg.shared.global [%0], [%1], 16;" :: "r"(dst), "l"(src) : "memory");
}
#define CP_COMMIT() asm volatile("cp.async.commit_group;" ::: "memory")
#define CP_WAIT0()  asm volatile("cp.async.wait_group 0;" ::: "memory")

__device__ __forceinline__ void mma_bf16(float* d, const uint32_t* a, const uint32_t* b) {
    asm volatile(
        "mma.sync.aligned.m16n8k16.row.col.f32.bf16.bf16.f32 "
        "{%0,%1,%2,%3}, {%4,%5,%6,%7}, {%8,%9}, {%0,%1,%2,%3};"
        : "+f"(d[0]), "+f"(d[1]), "+f"(d[2]), "+f"(d[3])
        : "r"(a[0]), "r"(a[1]), "r"(a[2]), "r"(a[3]), "r"(b[0]), "r"(b[1]));
}

// pack two fp32 -> bf16x2 (p0 in low half, p1 in high half)
__device__ __forceinline__ uint32_t pack_bf16(float p0, float p1) {
    uint32_t d;
    asm("cvt.rn.bf16x2.f32 %0, %1, %2;" : "=r"(d) : "f"(p1), "f"(p0));
    return d;
}
// split pair into hi word + lo word
__device__ __forceinline__ void split_pack(float p0, float p1, uint32_t& wh, uint32_t& wl) {
    wh = pack_bf16(p0, p1);
    float h0 = __int_as_float(wh << 16);
    float h1 = __int_as_float(wh & 0xFFFF0000u);
    wl = pack_bf16(p0 - h0, p1 - h1);
}

// e^x on the FFMA pipe (no MUFU): magic-round + deg-5 2^f poly + exponent add
__device__ __forceinline__ float fast_exp(float x) {
    x = fmaxf(x, -80.f);
    float t = fmaf(x, 1.4426950408889634f, 12582912.f);
    int   i = __float_as_int(t);
    float r = t - 12582912.f;
    float f = fmaf(x, 1.4426950408889634f, -r);
    float p = 1.3333558e-3f;
    p = fmaf(p, f, 9.6181291e-3f);
    p = fmaf(p, f, 5.5504109e-2f);
    p = fmaf(p, f, 2.4022651e-1f);
    p = fmaf(p, f, 6.9314718e-1f);
    p = fmaf(p, f, 1.0f);
    return __int_as_float(__float_as_int(p) + (i << 23));
}

// ===========================================================================
// Prep kernels
// ===========================================================================
__global__ __launch_bounds__(256) void split_x_kernel(const float* __restrict__ x)
{
    int i0 = (blockIdx.x * 256 + threadIdx.x) * 4;
    float4 v = *(const float4*)(x + i0);
    split_store(v.x, &g_xh[i0 + 0], &g_xl[i0 + 0]);
    split_store(v.y, &g_xh[i0 + 1], &g_xl[i0 + 1]);
    split_store(v.z, &g_xh[i0 + 2], &g_xl[i0 + 2]);
    split_store(v.w, &g_xh[i0 + 3], &g_xl[i0 + 3]);
}

__global__ __launch_bounds__(256) void conv_w_kernel(
    const float* __restrict__ Wq, const float* __restrict__ Wk, const float* __restrict__ Wv)
{
    int idx = blockIdx.x * 256 + threadIdx.x;
    int n  = idx >> 8;
    int d0 = (idx & 255) << 2;
    int sel = n >> 10, w = n & 1023, h = w >> 6, e = w & 63;
    const float* W = (sel == 0 ? Wq : (sel == 1 ? Wk : Wv));
    const float* p = W + (size_t)h * (D_IN * E) + e;
    #pragma unroll
    for (int i = 0; i < 4; i++) {
        float v = p[(size_t)(d0 + i) * E];
        split_store(v, &g_Wth[(size_t)n * D_IN + d0 + i], &g_Wtl[(size_t)n * D_IN + d0 + i]);
    }
}

__global__ __launch_bounds__(256) void conv_wo_kernel(const float* __restrict__ Wo)
{
    int idx = blockIdx.x * 256 + threadIdx.x;
    int n  = idx >> 8;
    int k0 = (idx & 255) << 2;
    #pragma unroll
    for (int i = 0; i < 4; i++) {
        float v = Wo[(size_t)(k0 + i) * D_IN + n];
        split_store(v, &g_Woth[(size_t)n * D_IN + k0 + i], &g_Wotl[(size_t)n * D_IN + k0 + i]);
    }
}

// ===========================================================================
// Split-bf16 GEMM on mma.sync: C = A[M,K] @ B[N,K]^T
// mode 0: QKV -> split bf16 per-head scatter; mode 1: fp32 dense out.
// ===========================================================================
#define TSTRIDE 40
#define TILE_E  (128 * TSTRIDE)
#define BUF_E   (4 * TILE_E)
#define GEMM_SMEM (2 * BUF_E * 2)

__global__ __launch_bounds__(256) void gemm_kernel(
    const __nv_bfloat16* __restrict__ Ah, const __nv_bfloat16* __restrict__ Al,
    const __nv_bfloat16* __restrict__ Bh, const __nv_bfloat16* __restrict__ Bl,
    int mode, float* __restrict__ outp)
{
    extern __shared__ __align__(16) __nv_bfloat16 sm[];
    const int tid  = threadIdx.x;
    const int wid  = tid >> 5, lane = tid & 31;
    const int grp  = lane >> 2, qid = lane & 3;
    const int n0   = blockIdx.x * 128, m0 = blockIdx.y * 128;
    const int wm   = (wid >> 1) * 32;
    const int wn   = (wid & 1) * 64;

    const int lr0 = tid >> 2;
    const int lc8 = (tid & 3) * 8;
    const __nv_bfloat16* srcs[4] = {Ah, Al, Bh, Bl};

    const uint32_t smb = smem_u32(sm);

    float acc[2][8][4] = {};

    #pragma unroll
    for (int t = 0; t < 4; t++) {
        const __nv_bfloat16* S = srcs[t] + (size_t)((t < 2 ? m0 : n0)) * D_IN + lc8;
        uint32_t dst = smb + (t * TILE_E) * 2 + lc8 * 2;
        cp16(dst + lr0 * (TSTRIDE * 2),        S + (size_t)lr0 * D_IN);
        cp16(dst + (lr0 + 64) * (TSTRIDE * 2), S + (size_t)(lr0 + 64) * D_IN);
    }
    CP_COMMIT();

    const int NC = D_IN / 32;
    for (int kc = 0; kc < NC; kc++) {
        const int cur = kc & 1;
        if (kc + 1 < NC) {
            const int nb = 1 - cur;
            #pragma unroll
            for (int t = 0; t < 4; t++) {
                const __nv_bfloat16* S = srcs[t] + (size_t)((t < 2 ? m0 : n0)) * D_IN
                                         + (kc + 1) * 32 + lc8;
                uint32_t dst = smb + (nb * BUF_E + t * TILE_E) * 2 + lc8 * 2;
                cp16(dst + lr0 * (TSTRIDE * 2),        S + (size_t)lr0 * D_IN);
                cp16(dst + (lr0 + 64) * (TSTRIDE * 2), S + (size_t)(lr0 + 64) * D_IN);
            }
            CP_COMMIT();
            asm volatile("cp.async.wait_group 1;" ::: "memory");
        } else {
            CP_WAIT0();
        }
        __syncthreads();

        const __nv_bfloat16* Asm_h = sm + cur * BUF_E;
        const __nv_bfloat16* Asm_l = Asm_h + TILE_E;
        const __nv_bfloat16* Bsm_h = Asm_h + 2 * TILE_E;
        const __nv_bfloat16* Bsm_l = Asm_h + 3 * TILE_E;

        #pragma unroll
        for (int k16 = 0; k16 < 32; k16 += 16) {
            uint32_t ah[2][4], al[2][4];
            #pragma unroll
            for (int mt = 0; mt < 2; mt++) {
                int r = wm + mt * 16 + grp;
                int c = k16 + qid * 2;
                ah[mt][0] = *(const uint32_t*)(Asm_h + r * TSTRIDE + c);
                ah[mt][1] = *(const uint32_t*)(Asm_h + (r + 8) * TSTRIDE + c);
                ah[mt][2] = *(const uint32_t*)(Asm_h + r * TSTRIDE + c + 8);
                ah[mt][3] = *(const uint32_t*)(Asm_h + (r + 8) * TSTRIDE + c + 8);
                al[mt][0] = *(const uint32_t*)(Asm_l + r * TSTRIDE + c);
                al[mt][1] = *(const uint32_t*)(Asm_l + (r + 8) * TSTRIDE + c);
                al[mt][2] = *(const uint32_t*)(Asm_l + r * TSTRIDE + c + 8);
                al[mt][3] = *(const uint32_t*)(Asm_l + (r + 8) * TSTRIDE + c + 8);
            }
            #pragma unroll
            for (int nt = 0; nt < 8; nt++) {
                int nr = wn + nt * 8 + grp;
                int c  = k16 + qid * 2;
                uint32_t bh[2], bl[2];
                bh[0] = *(const uint32_t*)(Bsm_h + nr * TSTRIDE + c);
                bh[1] = *(const uint32_t*)(Bsm_h + nr * TSTRIDE + c + 8);
                bl[0] = *(const uint32_t*)(Bsm_l + nr * TSTRIDE + c);
                bl[1] = *(const uint32_t*)(Bsm_l + nr * TSTRIDE + c + 8);
                #pragma unroll
                for (int mt = 0; mt < 2; mt++) {
                    mma_bf16(acc[mt][nt], ah[mt], bh);
                    mma_bf16(acc[mt][nt], ah[mt], bl);
                    mma_bf16(acc[mt][nt], al[mt], bh);
                }
            }
        }
        __syncthreads();
    }

    // epilogue
    #pragma unroll
    for (int mt = 0; mt < 2; mt++) {
        #pragma unroll
        for (int nt = 0; nt < 8; nt++) {
            int n = n0 + wn + nt * 8 + qid * 2;
            #pragma unroll
            for (int half = 0; half < 2; half++) {
                int m = m0 + wm + mt * 16 + grp + half * 8;
                float v0 = acc[mt][nt][half * 2], v1 = acc[mt][nt][half * 2 + 1];
                if (mode == 0) {
                    int sel = n >> 10, w = n & 1023, h = w >> 6, e = w & 63;
                    __nv_bfloat16* bh = (sel == 0 ? g_Qh : (sel == 1 ? g_Kh : g_Vh));
                    __nv_bfloat16* bl = (sel == 0 ? g_Ql : (sel == 1 ? g_Kl : g_Vl));
                    size_t o = ((size_t)h * N_TOK + m) * E + e;
                    uint32_t wh, wl;
                    split_pack(v0, v1, wh, wl);
                    *(uint32_t*)(bh + o) = wh;
                    *(uint32_t*)(bl + o) = wl;
                } else {
                    *(float2*)(outp + (size_t)m * D_IN + n) = make_float2(v0, v1);
                }
            }
        }
    }
}

// ===========================================================================
// HMMA flash attention. BQ=128 rows per CTA, one head; BK=128 key chunks.
// 256 threads (8 warps, warp = 16 q-rows). Split-bf16 S and PV (3 MMAs each).
// ===========================================================================
#define BQ 128
#define BK 128
// smem byte offsets (K row stride 72 bf16 = 144B; Vt row stride 136 bf16)
#define OFF_QH  0
#define OFF_QL  (OFF_QH + 128 * 144)
#define OFF_KH  (OFF_QL + 128 * 144)
#define OFF_KL  (OFF_KH + 128 * 144)
#define OFF_VRH (OFF_KL + 128 * 144)
#define OFF_VRL (OFF_VRH + 128 * 144)
#define OFF_VTH (OFF_VRL + 128 * 144)
#define OFF_VTL (OFF_VTH + 64 * 272)
#define ATTN_SMEM (OFF_VTL + 64 * 272)   // 145408 B

__global__ __launch_bounds__(256) void attn_kernel()
{
    extern __shared__ __align__(16) char smem[];
    const uint32_t smb = smem_u32(smem);
    const int tid = threadIdx.x, wid = tid >> 5, lane = tid & 31;
    const int grp = lane >> 2, qid = lane & 3;
    const int h = blockIdx.y;
    const int q0 = blockIdx.x * BQ;
    const int wm = wid * 16;

    const __nv_bfloat16* gQh = g_Qh + ((size_t)h * N_TOK + q0) * E;
    const __nv_bfloat16* gQl = g_Ql + ((size_t)h * N_TOK + q0) * E;
    const __nv_bfloat16* gKh = g_Kh + (size_t)h * N_TOK * E;
    const __nv_bfloat16* gKl = g_Kl + (size_t)h * N_TOK * E;
    const __nv_bfloat16* gVh = g_Vh + (size_t)h * N_TOK * E;
    const __nv_bfloat16* gVl = g_Vl + (size_t)h * N_TOK * E;

    // prologue: load Q + chunk 0 K/V
    #pragma unroll
    for (int i = 0; i < 4; i++) {
        int idx = i * 256 + tid, row = idx >> 3, ch = idx & 7;
        uint32_t so = row * 144 + ch * 16;
        size_t  go = (size_t)row * E + ch * 8;
        cp16(smb + OFF_QH + so, gQh + go);
        cp16(smb + OFF_QL + so, gQl + go);
        cp16(smb + OFF_KH + so, gKh + go);
        cp16(smb + OFF_KL + so, gKl + go);
        cp16(smb + OFF_VRH + so, gVh + go);
        cp16(smb + OFF_VRL + so, gVl + go);
    }
    CP_COMMIT();

    float accO[8][4] = {};
    float m0 = -1e30f, m1 = -1e30f, l0 = 0.f, l1 = 0.f;

    CP_WAIT0();
    __syncthreads();

    const char* qh  = smem + OFF_QH;
    const char* ql  = smem + OFF_QL;
    const char* kh  = smem + OFF_KH;
    const char* kl  = smem + OFF_KL;
    const char* vth = smem + OFF_VTH;
    const char* vtl = smem + OFF_VTL;

    for (int c = 0; c < N_TOK / BK; c++) {
        // ---- S = Q K^T (this chunk's K in smem)
        float accS[16][4] = {};
        #pragma unroll
        for (int k16 = 0; k16 < 4; k16++) {
            const int ab = (wm + grp) * 144 + (k16 * 16 + qid * 2) * 2;
            uint32_t ah[4], al[4];
            ah[0] = *(const uint32_t*)(qh + ab);
            ah[1] = *(const uint32_t*)(qh + ab + 8 * 144);
            ah[2] = *(const uint32_t*)(qh + ab + 16);
            ah[3] = *(const uint32_t*)(qh + ab + 8 * 144 + 16);
            al[0] = *(const uint32_t*)(ql + ab);
            al[1] = *(const uint32_t*)(ql + ab + 8 * 144);
            al[2] = *(const uint32_t*)(ql + ab + 16);
            al[3] = *(const uint32_t*)(ql + ab + 8 * 144 + 16);
            #pragma unroll
            for (int n8 = 0; n8 < 16; n8++) {
                const int bb = (n8 * 8 + grp) * 144 + (k16 * 16 + qid * 2) * 2;
                uint32_t bh2[2], bl2[2];
                bh2[0] = *(const uint32_t*)(kh + bb);
                bh2[1] = *(const uint32_t*)(kh + bb + 16);
                bl2[0] = *(const uint32_t*)(kl + bb);
                bl2[1] = *(const uint32_t*)(kl + bb + 16);
                mma_bf16(accS[n8], ah, bh2);
                mma_bf16(accS[n8], ah, bl2);
                mma_bf16(accS[n8], al, bh2);
            }
        }

        // ---- transpose V raw -> Vt (both hi and lo)
        #pragma unroll
        for (int a = 0; a < 2; a++) {
            const char* src = smem + (a ? OFF_VRL : OFF_VRH);
            char* dst = smem + (a ? OFF_VTL : OFF_VTH);
            #pragma unroll
            for (int i = 0; i < 16; i++) {
                int idx = i * 256 + tid, row = idx >> 5, ew = idx & 31;
                uint32_t w = *(const uint32_t*)(src + row * 144 + ew * 4);
                *(__nv_bfloat16*)(dst + ((2 * ew) * 136 + row) * 2)     = ((__nv_bfloat16*)&w)[0];
                *(__nv_bfloat16*)(dst + ((2 * ew + 1) * 136 + row) * 2) = ((__nv_bfloat16*)&w)[1];
            }
        }
        __syncthreads();   // all warps done with K / Vraw; Vt complete

        // ---- prefetch next chunk K/Vraw
        if (c + 1 < N_TOK / BK) {
            size_t cb = (size_t)(c + 1) * BK * E;
            #pragma unroll
            for (int i = 0; i < 4; i++) {
                int idx = i * 256 + tid, row = idx >> 3, ch = idx & 7;
                uint32_t so = row * 144 + ch * 16;
                size_t  go = cb + (size_t)row * E + ch * 8;
                cp16(smb + OFF_KH + so, gKh + go);
                cp16(smb + OFF_KL + so, gKl + go);
                cp16(smb + OFF_VRH + so, gVh + go);
                cp16(smb + OFF_VRL + so, gVl + go);
            }
            CP_COMMIT();
        }

        // ---- online softmax on accS (rows grp / grp+8, scale 1/8 in exp)
        float mx0 = -1e30f, mx1 = -1e30f;
        #pragma unroll
        for (int n8 = 0; n8 < 16; n8++) {
            mx0 = fmaxf(mx0, fmaxf(accS[n8][0], accS[n8][1]));
            mx1 = fmaxf(mx1, fmaxf(accS[n8][2], accS[n8][3]));
        }
        mx0 = fmaxf(mx0, __shfl_xor_sync(0xffffffff, mx0, 1));
        mx0 = fmaxf(mx0, __shfl_xor_sync(0xffffffff, mx0, 2));
        mx1 = fmaxf(mx1, __shfl_xor_sync(0xffffffff, mx1, 1));
        mx1 = fmaxf(mx1, __shfl_xor_sync(0xffffffff, mx1, 2));
        float mn0 = fmaxf(m0, mx0), mn1 = fmaxf(m1, mx1);
        float al0 = fast_exp((m0 - mn0) * 0.125f);
        float al1 = fast_exp((m1 - mn1) * 0.125f);
        m0 = mn0; m1 = mn1;
        float s0 = 0.f, s1 = 0.f;
        #pragma unroll
        for (int n8 = 0; n8 < 16; n8++) {
            accS[n8][0] = fast_exp((accS[n8][0] - m0) * 0.125f);
            accS[n8][1] = fast_exp((accS[n8][1] - m0) * 0.125f);
            accS[n8][2] = fast_exp((accS[n8][2] - m1) * 0.125f);
            accS[n8][3] = fast_exp((accS[n8][3] - m1) * 0.125f);
            s0 += accS[n8][0] + accS[n8][1];
            s1 += accS[n8][2] + accS[n8][3];
        }
        s0 += __shfl_xor_sync(0xffffffff, s0, 1);
        s0 += __shfl_xor_sync(0xffffffff, s0, 2);
        s1 += __shfl_xor_sync(0xffffffff, s1, 1);
        s1 += __shfl_xor_sync(0xffffffff, s1, 2);
        l0 = l0 * al0 + s0;
        l1 = l1 * al1 + s1;
        #pragma unroll
        for (int n8v = 0; n8v < 8; n8v++) {
            accO[n8v][0] *= al0; accO[n8v][1] *= al0;
            accO[n8v][2] *= al1; accO[n8v][3] *= al1;
        }

        // ---- PV: P fragments re-packed from accS in registers
        #pragma unroll
        for (int kk = 0; kk < 8; kk++) {
            uint32_t ah[4], al[4];
            split_pack(accS[2 * kk][0],     accS[2 * kk][1],     ah[0], al[0]);
            split_pack(accS[2 * kk][2],     accS[2 * kk][3],     ah[1], al[1]);
            split_pack(accS[2 * kk + 1][0], accS[2 * kk + 1][1], ah[2], al[2]);
            split_pack(accS[2 * kk + 1][2], accS[2 * kk + 1][3], ah[3], al[3]);
            #pragma unroll
            for (int n8v = 0; n8v < 8; n8v++) {
                const int bb = (n8v * 8 + grp) * 272 + (kk * 16 + qid * 2) * 2;
                uint32_t bh2[2], bl2[2];
                bh2[0] = *(const uint32_t*)(vth + bb);
                bh2[1] = *(const uint32_t*)(vth + bb + 16);
                bl2[0] = *(const uint32_t*)(vtl + bb);
                bl2[1] = *(const uint32_t*)(vtl + bb + 16);
                mma_bf16(accO[n8v], ah, bh2);
                mma_bf16(accO[n8v], ah, bl2);
                mma_bf16(accO[n8v], al, bh2);
            }
        }

        if (c + 1 < N_TOK / BK) CP_WAIT0();
        __syncthreads();
    }

    // ---- epilogue: normalize, split, store ctx [n][h*64+e]
    float inv0 = 1.f / l0, inv1 = 1.f / l1;
    const int row0 = q0 + wm + grp, row1 = row0 + 8;
    #pragma unroll
    for (int n8v = 0; n8v < 8; n8v++) {
        int colb = h * E + n8v * 8 + qid * 2;
        uint32_t wh, wl;
        split_pack(accO[n8v][0] * inv0, accO[n8v][1] * inv0, wh, wl);
        *(uint32_t*)(g_ctxh + (size_t)row0 * D_IN + colb) = wh;
        *(uint32_t*)(g_ctxl + (size_t)row0 * D_IN + colb) = wl;
        split_pack(accO[n8v][2] * inv1, accO[n8v][3] * inv1, wh, wl);
        *(uint32_t*)(g_ctxh + (size_t)row1 * D_IN + colb) = wh;
        *(uint32_t*)(g_ctxl + (size_t)row1 * D_IN + colb) = wl;
    }
}

// ===========================================================================
extern "C" void kernel_launch(void* const* d_in, const int* in_sizes, int n_in,
                              void* d_out, int out_size)
{
    const float* x  = (const float*)d_in[0];
    const float* Wq = (const float*)d_in[1];
    const float* Wk = (const float*)d_in[2];
    const float* Wv = (const float*)d_in[3];
    const float* Wo = (const float*)d_in[4];
    float* out = (float*)d_out;
    (void)in_sizes; (void)n_in; (void)out_size;

    cudaFuncSetAttribute(attn_kernel,
                         cudaFuncAttributeMaxDynamicSharedMemorySize, ATTN_SMEM);
    cudaFuncSetAttribute(gemm_kernel,
                         cudaFuncAttributeMaxDynamicSharedMemorySize, GEMM_SMEM);

    static __nv_bfloat16 *p_xh = nullptr, *p_xl, *p_Wth, *p_Wtl, *p_Woth, *p_Wotl, *p_ch, *p_cl;
    if (!p_xh) {
        cudaGetSymbolAddress((void**)&p_xh,  g_xh);
        cudaGetSymbolAddress((void**)&p_xl,  g_xl);
        cudaGetSymbolAddress((void**)&p_Wth, g_Wth);
        cudaGetSymbolAddress((void**)&p_Wtl, g_Wtl);
        cudaGetSymbolAddress((void**)&p_Woth, g_Woth);
        cudaGetSymbolAddress((void**)&p_Wotl, g_Wotl);
        cudaGetSymbolAddress((void**)&p_ch,  g_ctxh);
        cudaGetSymbolAddress((void**)&p_cl,  g_ctxl);
    }

    // prep
    split_x_kernel<<<(N_TOK * D_IN) / (256 * 4), 256>>>(x);
    conv_w_kernel<<<3072, 256>>>(Wq, Wk, Wv);
    conv_wo_kernel<<<1024, 256>>>(Wo);

    // QKV -> split bf16 Q/K/V
    dim3 g1(3072 / 128, N_TOK / 128);
    gemm_kernel<<<g1, 256, GEMM_SMEM>>>(p_xh, p_xl, p_Wth, p_Wtl, 0, nullptr);

    // HMMA flash attention
    dim3 g2(N_TOK / BQ, NH);
    attn_kernel<<<g2, 256, ATTN_SMEM>>>();

    // out = ctx @ Wo
    dim3 g3(D_IN / 128, N_TOK / 128);
    gemm_kernel<<<g3, 256, GEMM_SMEM>>>(p_ch, p_cl, p_Woth, p_Wotl, 1, out);
}

// round 6
// speedup vs baseline: 3.0303x; 1.2609x over previous
#include <cuda_runtime.h>
#include <cuda_bf16.h>
#include <math.h>
#include <stdint.h>

#define N_TOK 2048
#define D_IN  1024
#define NH    16
#define E     64

// ===========================================================================
// Device scratch (split bf16 hi/lo everywhere). V is stored TRANSPOSED.
// ===========================================================================
__device__ __nv_bfloat16 g_Qh[NH * N_TOK * E];
__device__ __nv_bfloat16 g_Ql[NH * N_TOK * E];
__device__ __nv_bfloat16 g_Kh[NH * N_TOK * E];
__device__ __nv_bfloat16 g_Kl[NH * N_TOK * E];
__device__ __nv_bfloat16 g_Vth[NH * E * N_TOK];   // [h][e][n]
__device__ __nv_bfloat16 g_Vtl[NH * E * N_TOK];

__device__ __nv_bfloat16 g_xh[N_TOK * D_IN];
__device__ __nv_bfloat16 g_xl[N_TOK * D_IN];
__device__ __nv_bfloat16 g_Wth[3072 * D_IN];   // [n][k], n = sel*1024 + h*64 + e
__device__ __nv_bfloat16 g_Wtl[3072 * D_IN];
__device__ __nv_bfloat16 g_Woth[D_IN * D_IN];  // [n][k] = Wo[k][n]
__device__ __nv_bfloat16 g_Wotl[D_IN * D_IN];
__device__ __nv_bfloat16 g_ctxh[N_TOK * D_IN];
__device__ __nv_bfloat16 g_ctxl[N_TOK * D_IN];

__device__ __forceinline__ void split_store(float v, __nv_bfloat16* hi, __nv_bfloat16* lo) {
    __nv_bfloat16 h = __float2bfloat16(v);
    *hi = h;
    *lo = __float2bfloat16(v - __bfloat162float(h));
}

__device__ __forceinline__ uint32_t smem_u32(const void* p) {
    uint32_t a;
    asm("{ .reg .u64 t; cvta.to.shared.u64 t, %1; cvt.u32.u64 %0, t; }" : "=r"(a) : "l"(p));
    return a;
}
__device__ __forceinline__ void cp16(uint32_t dst, const void* src) {
    asm volatile("cp.async.cg.shared.global [%0], [%1], 16;" :: "r"(dst), "l"(src) : "memory");
}
#define CP_COMMIT() asm volatile("cp.async.commit_group;" ::: "memory")
#define CP_WAIT0()  asm volatile("cp.async.wait_group 0;" ::: "memory")

__device__ __forceinline__ void mma_bf16(float* d, const uint32_t* a, const uint32_t* b) {
    asm volatile(
        "mma.sync.aligned.m16n8k16.row.col.f32.bf16.bf16.f32 "
        "{%0,%1,%2,%3}, {%4,%5,%6,%7}, {%8,%9}, {%0,%1,%2,%3};"
        : "+f"(d[0]), "+f"(d[1]), "+f"(d[2]), "+f"(d[3])
        : "r"(a[0]), "r"(a[1]), "r"(a[2]), "r"(a[3]), "r"(b[0]), "r"(b[1]));
}

__device__ __forceinline__ void ldsm_x4(uint32_t* r, uint32_t addr) {
    asm volatile("ldmatrix.sync.aligned.m8n8.x4.shared.b16 {%0,%1,%2,%3}, [%4];"
                 : "=r"(r[0]), "=r"(r[1]), "=r"(r[2]), "=r"(r[3]) : "r"(addr));
}

__device__ __forceinline__ uint32_t pack_bf16(float p0, float p1) {
    uint32_t d;
    asm("cvt.rn.bf16x2.f32 %0, %1, %2;" : "=r"(d) : "f"(p1), "f"(p0));
    return d;
}
__device__ __forceinline__ void split_pack(float p0, float p1, uint32_t& wh, uint32_t& wl) {
    wh = pack_bf16(p0, p1);
    float h0 = __int_as_float(wh << 16);
    float h1 = __int_as_float(wh & 0xFFFF0000u);
    wl = pack_bf16(p0 - h0, p1 - h1);
}

// e^x on the FFMA pipe
__device__ __forceinline__ float fast_exp(float x) {
    x = fmaxf(x, -80.f);
    float t = fmaf(x, 1.4426950408889634f, 12582912.f);
    int   i = __float_as_int(t);
    float r = t - 12582912.f;
    float f = fmaf(x, 1.4426950408889634f, -r);
    float p = 1.3333558e-3f;
    p = fmaf(p, f, 9.6181291e-3f);
    p = fmaf(p, f, 5.5504109e-2f);
    p = fmaf(p, f, 2.4022651e-1f);
    p = fmaf(p, f, 6.9314718e-1f);
    p = fmaf(p, f, 1.0f);
    return __int_as_float(__float_as_int(p) + (i << 23));
}

// ===========================================================================
// Prep kernels (smem tile transpose: coalesced both directions)
// ===========================================================================
__global__ __launch_bounds__(256) void split_x_kernel(const float* __restrict__ x)
{
    int i0 = (blockIdx.x * 256 + threadIdx.x) * 4;
    float4 v = *(const float4*)(x + i0);
    split_store(v.x, &g_xh[i0 + 0], &g_xl[i0 + 0]);
    split_store(v.y, &g_xh[i0 + 1], &g_xl[i0 + 1]);
    split_store(v.z, &g_xh[i0 + 2], &g_xl[i0 + 2]);
    split_store(v.w, &g_xh[i0 + 3], &g_xl[i0 + 3]);
}

__global__ __launch_bounds__(256) void conv_w_kernel(
    const float* __restrict__ Wq, const float* __restrict__ Wk, const float* __restrict__ Wv)
{
    __shared__ float t[64][65];
    const int tid = threadIdx.x;
    const int d0 = blockIdx.x * 64, h = blockIdx.y, sel = blockIdx.z;
    const float* W = (sel == 0 ? Wq : (sel == 1 ? Wk : Wv)) + (size_t)h * (D_IN * E);
    #pragma unroll
    for (int i = 0; i < 16; i++) {
        int idx = i * 256 + tid, r = idx >> 6, e = idx & 63;
        t[r][e] = W[(size_t)(d0 + r) * E + e];
    }
    __syncthreads();
    const int nb = sel * 1024 + h * 64;
    #pragma unroll
    for (int i = 0; i < 16; i++) {
        int idx = i * 256 + tid, er = idx >> 6, d = idx & 63;
        float v = t[d][er];
        size_t o = (size_t)(nb + er) * D_IN + d0 + d;
        split_store(v, &g_Wth[o], &g_Wtl[o]);
    }
}

__global__ __launch_bounds__(256) void conv_wo_kernel(const float* __restrict__ Wo)
{
    __shared__ float t[64][65];
    const int tid = threadIdx.x;
    const int k0 = blockIdx.x * 64, n0 = blockIdx.y * 64;
    #pragma unroll
    for (int i = 0; i < 16; i++) {
        int idx = i * 256 + tid, r = idx >> 6, c = idx & 63;
        t[r][c] = Wo[(size_t)(k0 + r) * D_IN + n0 + c];
    }
    __syncthreads();
    #pragma unroll
    for (int i = 0; i < 16; i++) {
        int idx = i * 256 + tid, nr = idx >> 6, k = idx & 63;
        float v = t[k][nr];
        size_t o = (size_t)(n0 + nr) * D_IN + k0 + k;
        split_store(v, &g_Woth[o], &g_Wotl[o]);
    }
}

// ===========================================================================
// Split-bf16 GEMM on mma.sync, ldmatrix fragments.
// mode 0: QKV scatter (Q/K per-head split bf16, V transposed); mode 1: fp32.
// ===========================================================================
#define TSTRB 80                         // bytes per smem tile row
#define TILE_B (128 * TSTRB)             // 10240 B per tile
#define BUF_B  (4 * TILE_B)              // 40960 B per buffer
#define GEMM_SMEM (2 * BUF_B)            // 81920 B

__global__ __launch_bounds__(256, 2) void gemm_kernel(
    const __nv_bfloat16* __restrict__ Ah, const __nv_bfloat16* __restrict__ Al,
    const __nv_bfloat16* __restrict__ Bh, const __nv_bfloat16* __restrict__ Bl,
    int mode, float* __restrict__ outp)
{
    extern __shared__ __align__(16) char smem[];
    const int tid  = threadIdx.x;
    const int wid  = tid >> 5, lane = tid & 31;
    const int grp  = lane >> 2, qid = lane & 3;
    const int n0   = blockIdx.x * 128, m0 = blockIdx.y * 128;
    const int wm   = (wid >> 1) * 32;
    const int wn   = (wid & 1) * 64;

    const int lr0 = tid >> 2;
    const int lc8 = (tid & 3) * 8;
    const __nv_bfloat16* srcs[4] = {Ah, Al, Bh, Bl};

    const uint32_t smb = smem_u32(smem);

    // ldmatrix lane-address components
    const int arow  = ((lane >> 3) & 1) * 8 + (lane & 7);
    const int acol  = ((lane >> 4) & 1) * 16;
    const int brow  = ((lane >> 4) & 1) * 8 + (lane & 7);
    const int bcol  = ((lane >> 3) & 1) * 16;

    float acc[2][8][4] = {};

    #pragma unroll
    for (int t = 0; t < 4; t++) {
        const __nv_bfloat16* S = srcs[t] + (size_t)((t < 2 ? m0 : n0)) * D_IN + lc8;
        uint32_t dst = smb + t * TILE_B + lc8 * 2;
        cp16(dst + lr0 * TSTRB,        S + (size_t)lr0 * D_IN);
        cp16(dst + (lr0 + 64) * TSTRB, S + (size_t)(lr0 + 64) * D_IN);
    }
    CP_COMMIT();

    const int NC = D_IN / 32;
    for (int kc = 0; kc < NC; kc++) {
        const int cur = kc & 1;
        if (kc + 1 < NC) {
            const int nb = 1 - cur;
            #pragma unroll
            for (int t = 0; t < 4; t++) {
                const __nv_bfloat16* S = srcs[t] + (size_t)((t < 2 ? m0 : n0)) * D_IN
                                         + (kc + 1) * 32 + lc8;
                uint32_t dst = smb + nb * BUF_B + t * TILE_B + lc8 * 2;
                cp16(dst + lr0 * TSTRB,        S + (size_t)lr0 * D_IN);
                cp16(dst + (lr0 + 64) * TSTRB, S + (size_t)(lr0 + 64) * D_IN);
            }
            CP_COMMIT();
            asm volatile("cp.async.wait_group 1;" ::: "memory");
        } else {
            CP_WAIT0();
        }
        __syncthreads();

        const uint32_t Ah_b = smb + cur * BUF_B;
        const uint32_t Al_b = Ah_b + TILE_B;
        const uint32_t Bh_b = Ah_b + 2 * TILE_B;
        const uint32_t Bl_b = Ah_b + 3 * TILE_B;

        #pragma unroll
        for (int k16 = 0; k16 < 2; k16++) {
            const int cb = k16 * 32 + acol;
            uint32_t ah0[4], ah1[4], al0[4], al1[4];
            ldsm_x4(ah0, Ah_b + (wm + arow) * TSTRB + cb);
            ldsm_x4(ah1, Ah_b + (wm + 16 + arow) * TSTRB + cb);
            ldsm_x4(al0, Al_b + (wm + arow) * TSTRB + cb);
            ldsm_x4(al1, Al_b + (wm + 16 + arow) * TSTRB + cb);
            const int cbb = k16 * 32 + bcol;
            #pragma unroll
            for (int np = 0; np < 4; np++) {
                uint32_t bh[4], bl[4];
                ldsm_x4(bh, Bh_b + (wn + np * 16 + brow) * TSTRB + cbb);
                ldsm_x4(bl, Bl_b + (wn + np * 16 + brow) * TSTRB + cbb);
                mma_bf16(acc[0][2*np],   ah0, bh);
                mma_bf16(acc[0][2*np],   ah0, bl);
                mma_bf16(acc[0][2*np],   al0, bh);
                mma_bf16(acc[0][2*np+1], ah0, bh + 2);
                mma_bf16(acc[0][2*np+1], ah0, bl + 2);
                mma_bf16(acc[0][2*np+1], al0, bh + 2);
                mma_bf16(acc[1][2*np],   ah1, bh);
                mma_bf16(acc[1][2*np],   ah1, bl);
                mma_bf16(acc[1][2*np],   al1, bh);
                mma_bf16(acc[1][2*np+1], ah1, bh + 2);
                mma_bf16(acc[1][2*np+1], ah1, bl + 2);
                mma_bf16(acc[1][2*np+1], al1, bh + 2);
            }
        }
        __syncthreads();
    }

    // epilogue
    #pragma unroll
    for (int mt = 0; mt < 2; mt++) {
        #pragma unroll
        for (int nt = 0; nt < 8; nt++) {
            int n = n0 + wn + nt * 8 + qid * 2;
            #pragma unroll
            for (int half = 0; half < 2; half++) {
                int m = m0 + wm + mt * 16 + grp + half * 8;
                float v0 = acc[mt][nt][half * 2], v1 = acc[mt][nt][half * 2 + 1];
                if (mode == 0) {
                    int sel = n >> 10, w = n & 1023, h = w >> 6, e = w & 63;
                    if (sel < 2) {
                        __nv_bfloat16* bh = (sel == 0 ? g_Qh : g_Kh);
                        __nv_bfloat16* bl = (sel == 0 ? g_Ql : g_Kl);
                        size_t o = ((size_t)h * N_TOK + m) * E + e;
                        uint32_t wh, wl;
                        split_pack(v0, v1, wh, wl);
                        *(uint32_t*)(bh + o) = wh;
                        *(uint32_t*)(bl + o) = wl;
                    } else {
                        size_t o = ((size_t)h * E + e) * N_TOK + m;
                        split_store(v0, &g_Vth[o],        &g_Vtl[o]);
                        split_store(v1, &g_Vth[o + N_TOK], &g_Vtl[o + N_TOK]);
                    }
                } else {
                    *(float2*)(outp + (size_t)m * D_IN + n) = make_float2(v0, v1);
                }
            }
        }
    }
}

// ===========================================================================
// HMMA flash attention, ldmatrix fragments, double-buffered K/Vt, no
// in-kernel transpose (V pre-transposed in global).
// ===========================================================================
#define BQ 128
#define BK 128
#define KSTR 144      // Q/K smem row bytes (64 bf16 + pad)
#define VSTR 272      // Vt smem row bytes (128 bf16 + pad)
#define OFF_Q   0
#define QBUF    (128 * KSTR)                 // 18432 per hi/lo
#define OFF_K0  (2 * QBUF)                   // 36864
#define KBUF    (128 * KSTR)                 // per hi/lo
#define OFF_K1  (OFF_K0 + 2 * KBUF)          // 73728
#define OFF_VT0 (OFF_K1 + 2 * KBUF)          // 110592
#define VBUF    (64 * VSTR)                  // 17408 per hi/lo
#define OFF_VT1 (OFF_VT0 + 2 * VBUF)         // 145408
#define ATTN_SMEM (OFF_VT1 + 2 * VBUF)       // 180224

__global__ __launch_bounds__(256) void attn_kernel()
{
    extern __shared__ __align__(16) char smem[];
    const uint32_t smb = smem_u32(smem);
    const int tid = threadIdx.x, wid = tid >> 5, lane = tid & 31;
    const int grp = lane >> 2, qid = lane & 3;
    const int h = blockIdx.y;
    const int q0 = blockIdx.x * BQ;
    const int wm = wid * 16;

    const __nv_bfloat16* gQh = g_Qh + ((size_t)h * N_TOK + q0) * E;
    const __nv_bfloat16* gQl = g_Ql + ((size_t)h * N_TOK + q0) * E;
    const __nv_bfloat16* gKh = g_Kh + (size_t)h * N_TOK * E;
    const __nv_bfloat16* gKl = g_Kl + (size_t)h * N_TOK * E;
    const __nv_bfloat16* gVth = g_Vth + (size_t)h * E * N_TOK;
    const __nv_bfloat16* gVtl = g_Vtl + (size_t)h * E * N_TOK;

    // ldmatrix lane-address components
    const int arow = ((lane >> 3) & 1) * 8 + (lane & 7);
    const int acol = ((lane >> 4) & 1) * 16;
    const int brow = ((lane >> 4) & 1) * 8 + (lane & 7);
    const int bcol = ((lane >> 3) & 1) * 16;

    // prologue: Q + chunk 0 K + chunk 0 Vt
    #pragma unroll
    for (int i = 0; i < 4; i++) {
        int idx = i * 256 + tid;
        int row = idx >> 3, ch = idx & 7;
        uint32_t so = row * KSTR + ch * 16;
        size_t  go = (size_t)row * E + ch * 8;
        cp16(smb + OFF_Q + so,            gQh + go);
        cp16(smb + OFF_Q + QBUF + so,     gQl + go);
        cp16(smb + OFF_K0 + so,           gKh + go);
        cp16(smb + OFF_K0 + KBUF + so,    gKl + go);
        int vrow = idx >> 4, vch = idx & 15;
        uint32_t vso = vrow * VSTR + vch * 16;
        size_t  vgo = (size_t)vrow * N_TOK + vch * 8;
        cp16(smb + OFF_VT0 + vso,         gVth + vgo);
        cp16(smb + OFF_VT0 + VBUF + vso,  gVtl + vgo);
    }
    CP_COMMIT();

    float accO[8][4] = {};
    float m0 = -1e30f, m1 = -1e30f, l0 = 0.f, l1 = 0.f;

    CP_WAIT0();
    __syncthreads();

    for (int c = 0; c < N_TOK / BK; c++) {
        const uint32_t kb  = smb + ((c & 1) ? OFF_K1 : OFF_K0);
        const uint32_t vtb = smb + ((c & 1) ? OFF_VT1 : OFF_VT0);

        // ---- S = Q K^T
        float accS[16][4] = {};
        #pragma unroll
        for (int k16 = 0; k16 < 4; k16++) {
            uint32_t ah[4], al[4];
            const uint32_t aaddr = smb + OFF_Q + (wm + arow) * KSTR + k16 * 32 + acol;
            ldsm_x4(ah, aaddr);
            ldsm_x4(al, aaddr + QBUF);
            #pragma unroll
            for (int np = 0; np < 8; np++) {
                uint32_t bh[4], bl[4];
                const uint32_t baddr = kb + (np * 16 + brow) * KSTR + k16 * 32 + bcol;
                ldsm_x4(bh, baddr);
                ldsm_x4(bl, baddr + KBUF);
                mma_bf16(accS[2*np],   ah, bh);
                mma_bf16(accS[2*np],   ah, bl);
                mma_bf16(accS[2*np],   al, bh);
                mma_bf16(accS[2*np+1], ah, bh + 2);
                mma_bf16(accS[2*np+1], ah, bl + 2);
                mma_bf16(accS[2*np+1], al, bh + 2);
            }
        }

        // ---- prefetch next chunk K/Vt into other buffer
        if (c + 1 < N_TOK / BK) {
            const uint32_t kn  = smb + ((c & 1) ? OFF_K0 : OFF_K1);
            const uint32_t vtn = smb + ((c & 1) ? OFF_VT0 : OFF_VT1);
            #pragma unroll
            for (int i = 0; i < 4; i++) {
                int idx = i * 256 + tid;
                int row = idx >> 3, ch = idx & 7;
                uint32_t so = row * KSTR + ch * 16;
                size_t  go = ((size_t)(c + 1) * BK + row) * E + ch * 8;
                cp16(kn + so,        gKh + go);
                cp16(kn + KBUF + so, gKl + go);
                int vrow = idx >> 4, vch = idx & 15;
                uint32_t vso = vrow * VSTR + vch * 16;
                size_t  vgo = (size_t)vrow * N_TOK + (c + 1) * BK + vch * 8;
                cp16(vtn + vso,        gVth + vgo);
                cp16(vtn + VBUF + vso, gVtl + vgo);
            }
            CP_COMMIT();
        }

        // ---- online softmax
        float mx0 = -1e30f, mx1 = -1e30f;
        #pragma unroll
        for (int n8 = 0; n8 < 16; n8++) {
            mx0 = fmaxf(mx0, fmaxf(accS[n8][0], accS[n8][1]));
            mx1 = fmaxf(mx1, fmaxf(accS[n8][2], accS[n8][3]));
        }
        mx0 = fmaxf(mx0, __shfl_xor_sync(0xffffffff, mx0, 1));
        mx0 = fmaxf(mx0, __shfl_xor_sync(0xffffffff, mx0, 2));
        mx1 = fmaxf(mx1, __shfl_xor_sync(0xffffffff, mx1, 1));
        mx1 = fmaxf(mx1, __shfl_xor_sync(0xffffffff, mx1, 2));
        float mn0 = fmaxf(m0, mx0), mn1 = fmaxf(m1, mx1);
        float al0 = fast_exp((m0 - mn0) * 0.125f);
        float al1 = fast_exp((m1 - mn1) * 0.125f);
        m0 = mn0; m1 = mn1;
        float s0 = 0.f, s1 = 0.f;
        #pragma unroll
        for (int n8 = 0; n8 < 16; n8++) {
            accS[n8][0] = fast_exp((accS[n8][0] - m0) * 0.125f);
            accS[n8][1] = fast_exp((accS[n8][1] - m0) * 0.125f);
            accS[n8][2] = fast_exp((accS[n8][2] - m1) * 0.125f);
            accS[n8][3] = fast_exp((accS[n8][3] - m1) * 0.125f);
            s0 += accS[n8][0] + accS[n8][1];
            s1 += accS[n8][2] + accS[n8][3];
        }
        s0 += __shfl_xor_sync(0xffffffff, s0, 1);
        s0 += __shfl_xor_sync(0xffffffff, s0, 2);
        s1 += __shfl_xor_sync(0xffffffff, s1, 1);
        s1 += __shfl_xor_sync(0xffffffff, s1, 2);
        l0 = l0 * al0 + s0;
        l1 = l1 * al1 + s1;
        #pragma unroll
        for (int n8v = 0; n8v < 8; n8v++) {
            accO[n8v][0] *= al0; accO[n8v][1] *= al0;
            accO[n8v][2] *= al1; accO[n8v][3] *= al1;
        }

        // ---- PV (P fragments re-packed from registers; Vt from smem)
        #pragma unroll
        for (int kk = 0; kk < 8; kk++) {
            uint32_t ah[4], al[4];
            split_pack(accS[2 * kk][0],     accS[2 * kk][1],     ah[0], al[0]);
            split_pack(accS[2 * kk][2],     accS[2 * kk][3],     ah[1], al[1]);
            split_pack(accS[2 * kk + 1][0], accS[2 * kk + 1][1], ah[2], al[2]);
            split_pack(accS[2 * kk + 1][2], accS[2 * kk + 1][3], ah[3], al[3]);
            #pragma unroll
            for (int np = 0; np < 4; np++) {
                uint32_t bh[4], bl[4];
                const uint32_t baddr = vtb + (np * 16 + brow) * VSTR + kk * 32 + bcol;
                ldsm_x4(bh, baddr);
                ldsm_x4(bl, baddr + VBUF);
                mma_bf16(accO[2*np],   ah, bh);
                mma_bf16(accO[2*np],   ah, bl);
                mma_bf16(accO[2*np],   al, bh);
                mma_bf16(accO[2*np+1], ah, bh + 2);
                mma_bf16(accO[2*np+1], ah, bl + 2);
                mma_bf16(accO[2*np+1], al, bh + 2);
            }
        }

        if (c + 1 < N_TOK / BK) {
            CP_WAIT0();
            __syncthreads();
        }
    }

    // ---- epilogue
    float inv0 = 1.f / l0, inv1 = 1.f / l1;
    const int row0 = q0 + wm + grp, row1 = row0 + 8;
    #pragma unroll
    for (int n8v = 0; n8v < 8; n8v++) {
        int colb = h * E + n8v * 8 + qid * 2;
        uint32_t wh, wl;
        split_pack(accO[n8v][0] * inv0, accO[n8v][1] * inv0, wh, wl);
        *(uint32_t*)(g_ctxh + (size_t)row0 * D_IN + colb) = wh;
        *(uint32_t*)(g_ctxl + (size_t)row0 * D_IN + colb) = wl;
        split_pack(accO[n8v][2] * inv1, accO[n8v][3] * inv1, wh, wl);
        *(uint32_t*)(g_ctxh + (size_t)row1 * D_IN + colb) = wh;
        *(uint32_t*)(g_ctxl + (size_t)row1 * D_IN + colb) = wl;
    }
}

// ===========================================================================
extern "C" void kernel_launch(void* const* d_in, const int* in_sizes, int n_in,
                              void* d_out, int out_size)
{
    const float* x  = (const float*)d_in[0];
    const float* Wq = (const float*)d_in[1];
    const float* Wk = (const float*)d_in[2];
    const float* Wv = (const float*)d_in[3];
    const float* Wo = (const float*)d_in[4];
    float* out = (float*)d_out;
    (void)in_sizes; (void)n_in; (void)out_size;

    cudaFuncSetAttribute(attn_kernel,
                         cudaFuncAttributeMaxDynamicSharedMemorySize, ATTN_SMEM);
    cudaFuncSetAttribute(gemm_kernel,
                         cudaFuncAttributeMaxDynamicSharedMemorySize, GEMM_SMEM);

    static __nv_bfloat16 *p_xh = nullptr, *p_xl, *p_Wth, *p_Wtl, *p_Woth, *p_Wotl, *p_ch, *p_cl;
    if (!p_xh) {
        cudaGetSymbolAddress((void**)&p_xh,  g_xh);
        cudaGetSymbolAddress((void**)&p_xl,  g_xl);
        cudaGetSymbolAddress((void**)&p_Wth, g_Wth);
        cudaGetSymbolAddress((void**)&p_Wtl, g_Wtl);
        cudaGetSymbolAddress((void**)&p_Woth, g_Woth);
        cudaGetSymbolAddress((void**)&p_Wotl, g_Wotl);
        cudaGetSymbolAddress((void**)&p_ch,  g_ctxh);
        cudaGetSymbolAddress((void**)&p_cl,  g_ctxl);
    }

    // prep
    split_x_kernel<<<(N_TOK * D_IN) / (256 * 4), 256>>>(x);
    dim3 gw(D_IN / 64, NH, 3);
    conv_w_kernel<<<gw, 256>>>(Wq, Wk, Wv);
    dim3 gwo(D_IN / 64, D_IN / 64);
    conv_wo_kernel<<<gwo, 256>>>(Wo);

    // QKV -> split bf16 Q/K + transposed V
    dim3 g1(3072 / 128, N_TOK / 128);
    gemm_kernel<<<g1, 256, GEMM_SMEM>>>(p_xh, p_xl, p_Wth, p_Wtl, 0, nullptr);

    // HMMA flash attention
    dim3 g2(N_TOK / BQ, NH);
    attn_kernel<<<g2, 256, ATTN_SMEM>>>();

    // out = ctx @ Wo
    dim3 g3(D_IN / 128, N_TOK / 128);
    gemm_kernel<<<g3, 256, GEMM_SMEM>>>(p_ch, p_cl, p_Woth, p_Wotl, 1, out);
}

// round 8
// speedup vs baseline: 3.1707x; 1.0463x over previous
#include <cuda_runtime.h>
#include <cuda_bf16.h>
#include <math.h>
#include <stdint.h>

#define N_TOK 2048
#define D_IN  1024
#define NH    16
#define E     64

// ===========================================================================
// Device scratch (split bf16 hi/lo everywhere). V is stored TRANSPOSED.
// ===========================================================================
__device__ __nv_bfloat16 g_Qh[NH * N_TOK * E];
__device__ __nv_bfloat16 g_Ql[NH * N_TOK * E];
__device__ __nv_bfloat16 g_Kh[NH * N_TOK * E];
__device__ __nv_bfloat16 g_Kl[NH * N_TOK * E];
__device__ __nv_bfloat16 g_Vth[NH * E * N_TOK];   // [h][e][n]
__device__ __nv_bfloat16 g_Vtl[NH * E * N_TOK];

__device__ __nv_bfloat16 g_xh[N_TOK * D_IN];
__device__ __nv_bfloat16 g_xl[N_TOK * D_IN];
__device__ __nv_bfloat16 g_Wth[3072 * D_IN];   // [n][k]
__device__ __nv_bfloat16 g_Wtl[3072 * D_IN];
__device__ __nv_bfloat16 g_Woth[D_IN * D_IN];  // [n][k] = Wo[k][n]
__device__ __nv_bfloat16 g_Wotl[D_IN * D_IN];
__device__ __nv_bfloat16 g_ctxh[N_TOK * D_IN];
__device__ __nv_bfloat16 g_ctxl[N_TOK * D_IN];

__device__ __forceinline__ void split_store(float v, __nv_bfloat16* hi, __nv_bfloat16* lo) {
    __nv_bfloat16 h = __float2bfloat16(v);
    *hi = h;
    *lo = __float2bfloat16(v - __bfloat162float(h));
}

__device__ __forceinline__ uint32_t smem_u32(const void* p) {
    uint32_t a;
    asm("{ .reg .u64 t; cvta.to.shared.u64 t, %1; cvt.u32.u64 %0, t; }" : "=r"(a) : "l"(p));
    return a;
}
__device__ __forceinline__ void cp16(uint32_t dst, const void* src) {
    asm volatile("cp.async.cg.shared.global [%0], [%1], 16;" :: "r"(dst), "l"(src) : "memory");
}
#define CP_COMMIT() asm volatile("cp.async.commit_group;" ::: "memory")
#define CP_WAIT0()  asm volatile("cp.async.wait_group 0;" ::: "memory")

__device__ __forceinline__ void mma_bf16(float* d, const uint32_t* a, const uint32_t* b) {
    asm volatile(
        "mma.sync.aligned.m16n8k16.row.col.f32.bf16.bf16.f32 "
        "{%0,%1,%2,%3}, {%4,%5,%6,%7}, {%8,%9}, {%0,%1,%2,%3};"
        : "+f"(d[0]), "+f"(d[1]), "+f"(d[2]), "+f"(d[3])
        : "r"(a[0]), "r"(a[1]), "r"(a[2]), "r"(a[3]), "r"(b[0]), "r"(b[1]));
}

__device__ __forceinline__ void ldsm_x4(uint32_t* r, uint32_t addr) {
    asm volatile("ldmatrix.sync.aligned.m8n8.x4.shared.b16 {%0,%1,%2,%3}, [%4];"
                 : "=r"(r[0]), "=r"(r[1]), "=r"(r[2]), "=r"(r[3]) : "r"(addr));
}

__device__ __forceinline__ uint32_t pack_bf16(float p0, float p1) {
    uint32_t d;
    asm("cvt.rn.bf16x2.f32 %0, %1, %2;" : "=r"(d) : "f"(p1), "f"(p0));
    return d;
}
__device__ __forceinline__ void split_pack(float p0, float p1, uint32_t& wh, uint32_t& wl) {
    wh = pack_bf16(p0, p1);
    float h0 = __int_as_float(wh << 16);
    float h1 = __int_as_float(wh & 0xFFFF0000u);
    wl = pack_bf16(p0 - h0, p1 - h1);
}

// e^x on the FFMA pipe
__device__ __forceinline__ float fast_exp(float x) {
    x = fmaxf(x, -80.f);
    float t = fmaf(x, 1.4426950408889634f, 12582912.f);
    int   i = __float_as_int(t);
    float r = t - 12582912.f;
    float f = fmaf(x, 1.4426950408889634f, -r);
    float p = 1.3333558e-3f;
    p = fmaf(p, f, 9.6181291e-3f);
    p = fmaf(p, f, 5.5504109e-2f);
    p = fmaf(p, f, 2.4022651e-1f);
    p = fmaf(p, f, 6.9314718e-1f);
    p = fmaf(p, f, 1.0f);
    return __int_as_float(__float_as_int(p) + (i << 23));
}

// ===========================================================================
// Prep kernels
// ===========================================================================
__global__ __launch_bounds__(256) void split_x_kernel(const float* __restrict__ x)
{
    int i0 = (blockIdx.x * 256 + threadIdx.x) * 4;
    float4 v = *(const float4*)(x + i0);
    split_store(v.x, &g_xh[i0 + 0], &g_xl[i0 + 0]);
    split_store(v.y, &g_xh[i0 + 1], &g_xl[i0 + 1]);
    split_store(v.z, &g_xh[i0 + 2], &g_xl[i0 + 2]);
    split_store(v.w, &g_xh[i0 + 3], &g_xl[i0 + 3]);
}

__global__ __launch_bounds__(256) void conv_w_kernel(
    const float* __restrict__ Wq, const float* __restrict__ Wk, const float* __restrict__ Wv)
{
    __shared__ float t[64][65];
    const int tid = threadIdx.x;
    const int d0 = blockIdx.x * 64, h = blockIdx.y, sel = blockIdx.z;
    const float* W = (sel == 0 ? Wq : (sel == 1 ? Wk : Wv)) + (size_t)h * (D_IN * E);
    #pragma unroll
    for (int i = 0; i < 16; i++) {
        int idx = i * 256 + tid, r = idx >> 6, e = idx & 63;
        t[r][e] = W[(size_t)(d0 + r) * E + e];
    }
    __syncthreads();
    const int nb = sel * 1024 + h * 64;
    #pragma unroll
    for (int i = 0; i < 16; i++) {
        int idx = i * 256 + tid, er = idx >> 6, d = idx & 63;
        float v = t[d][er];
        size_t o = (size_t)(nb + er) * D_IN + d0 + d;
        split_store(v, &g_Wth[o], &g_Wtl[o]);
    }
}

__global__ __launch_bounds__(256) void conv_wo_kernel(const float* __restrict__ Wo)
{
    __shared__ float t[64][65];
    const int tid = threadIdx.x;
    const int k0 = blockIdx.x * 64, n0 = blockIdx.y * 64;
    #pragma unroll
    for (int i = 0; i < 16; i++) {
        int idx = i * 256 + tid, r = idx >> 6, c = idx & 63;
        t[r][c] = Wo[(size_t)(k0 + r) * D_IN + n0 + c];
    }
    __syncthreads();
    #pragma unroll
    for (int i = 0; i < 16; i++) {
        int idx = i * 256 + tid, nr = idx >> 6, k = idx & 63;
        float v = t[k][nr];
        size_t o = (size_t)(n0 + nr) * D_IN + k0 + k;
        split_store(v, &g_Woth[o], &g_Wotl[o]);
    }
}

// ===========================================================================
// Split-bf16 GEMM, templated on BN (CTA tile 128 x BN). 8 warps: 4(M) x 2(N).
// ===========================================================================
#define TSTRB 80
#define ATILE_B (128 * TSTRB)            // 10240

template<int BN>
__global__ __launch_bounds__(256, 2) void gemm_kernel(
    const __nv_bfloat16* __restrict__ Ah, const __nv_bfloat16* __restrict__ Al,
    const __nv_bfloat16* __restrict__ Bh, const __nv_bfloat16* __restrict__ Bl,
    int mode, float* __restrict__ outp)
{
    constexpr int BTILE_B = BN * TSTRB;
    constexpr int BUF_B   = 2 * ATILE_B + 2 * BTILE_B;
    constexpr int NP      = BN / 32;
    extern __shared__ __align__(16) char smem[];
    const int tid  = threadIdx.x;
    const int wid  = tid >> 5, lane = tid & 31;
    const int grp  = lane >> 2, qid = lane & 3;
    const int n0   = blockIdx.x * BN, m0 = blockIdx.y * 128;
    const int wm   = (wid >> 1) * 32;
    const int wn   = (wid & 1) * (BN / 2);

    const uint32_t smb = smem_u32(smem);

    const int arow  = ((lane >> 3) & 1) * 8 + (lane & 7);
    const int acol  = ((lane >> 4) & 1) * 16;
    const int brow  = ((lane >> 4) & 1) * 8 + (lane & 7);
    const int bcol  = ((lane >> 3) & 1) * 16;

    float acc[2][2 * NP][4] = {};

    auto load_tiles = [&](int buf, int kc) {
        const uint32_t bb = smb + buf * BUF_B;
        #pragma unroll
        for (int i = 0; i < 4; i++) {
            int c = i * 256 + tid;
            int t = c >> 9, w = c & 511, row = w >> 2, ch = w & 3;
            const __nv_bfloat16* S = (t ? Al : Ah);
            cp16(bb + t * ATILE_B + row * TSTRB + ch * 16,
                 S + (size_t)(m0 + row) * D_IN + kc * 32 + ch * 8);
        }
        #pragma unroll
        for (int i = 0; i < (8 * BN) / 256; i++) {
            int c = i * 256 + tid;
            int t = c / (BN * 4), w = c % (BN * 4), row = w >> 2, ch = w & 3;
            const __nv_bfloat16* S = (t ? Bl : Bh);
            cp16(bb + 2 * ATILE_B + t * BTILE_B + row * TSTRB + ch * 16,
                 S + (size_t)(n0 + row) * D_IN + kc * 32 + ch * 8);
        }
    };

    load_tiles(0, 0);
    CP_COMMIT();

    const int NC = D_IN / 32;
    for (int kc = 0; kc < NC; kc++) {
        const int cur = kc & 1;
        if (kc + 1 < NC) {
            load_tiles(1 - cur, kc + 1);
            CP_COMMIT();
            asm volatile("cp.async.wait_group 1;" ::: "memory");
        } else {
            CP_WAIT0();
        }
        __syncthreads();

        const uint32_t Ah_b = smb + cur * BUF_B;
        const uint32_t Al_b = Ah_b + ATILE_B;
        const uint32_t Bh_b = Ah_b + 2 * ATILE_B;
        const uint32_t Bl_b = Bh_b + BTILE_B;

        #pragma unroll
        for (int k16 = 0; k16 < 2; k16++) {
            const int cb = k16 * 32 + acol;
            uint32_t ah0[4], ah1[4], al0[4], al1[4];
            ldsm_x4(ah0, Ah_b + (wm + arow) * TSTRB + cb);
            ldsm_x4(ah1, Ah_b + (wm + 16 + arow) * TSTRB + cb);
            ldsm_x4(al0, Al_b + (wm + arow) * TSTRB + cb);
            ldsm_x4(al1, Al_b + (wm + 16 + arow) * TSTRB + cb);
            const int cbb = k16 * 32 + bcol;
            #pragma unroll
            for (int np = 0; np < NP; np++) {
                uint32_t bh[4], bl[4];
                ldsm_x4(bh, Bh_b + (wn + np * 16 + brow) * TSTRB + cbb);
                ldsm_x4(bl, Bl_b + (wn + np * 16 + brow) * TSTRB + cbb);
                mma_bf16(acc[0][2*np],   ah0, bh);
                mma_bf16(acc[0][2*np],   ah0, bl);
                mma_bf16(acc[0][2*np],   al0, bh);
                mma_bf16(acc[0][2*np+1], ah0, bh + 2);
                mma_bf16(acc[0][2*np+1], ah0, bl + 2);
                mma_bf16(acc[0][2*np+1], al0, bh + 2);
                mma_bf16(acc[1][2*np],   ah1, bh);
                mma_bf16(acc[1][2*np],   ah1, bl);
                mma_bf16(acc[1][2*np],   al1, bh);
                mma_bf16(acc[1][2*np+1], ah1, bh + 2);
                mma_bf16(acc[1][2*np+1], ah1, bl + 2);
                mma_bf16(acc[1][2*np+1], al1, bh + 2);
            }
        }
        __syncthreads();
    }

    // epilogue
    #pragma unroll
    for (int mt = 0; mt < 2; mt++) {
        #pragma unroll
        for (int nt = 0; nt < 2 * NP; nt++) {
            int n = n0 + wn + nt * 8 + qid * 2;
            #pragma unroll
            for (int half = 0; half < 2; half++) {
                int m = m0 + wm + mt * 16 + grp + half * 8;
                float v0 = acc[mt][nt][half * 2], v1 = acc[mt][nt][half * 2 + 1];
                if (mode == 0) {
                    int sel = n >> 10, w = n & 1023, h = w >> 6, e = w & 63;
                    if (sel < 2) {
                        __nv_bfloat16* bh = (sel == 0 ? g_Qh : g_Kh);
                        __nv_bfloat16* bl = (sel == 0 ? g_Ql : g_Kl);
                        size_t o = ((size_t)h * N_TOK + m) * E + e;
                        uint32_t wh, wl;
                        split_pack(v0, v1, wh, wl);
                        *(uint32_t*)(bh + o) = wh;
                        *(uint32_t*)(bl + o) = wl;
                    } else {
                        size_t o = ((size_t)h * E + e) * N_TOK + m;
                        split_store(v0, &g_Vth[o],         &g_Vtl[o]);
                        split_store(v1, &g_Vth[o + N_TOK], &g_Vtl[o + N_TOK]);
                    }
                } else {
                    *(float2*)(outp + (size_t)m * D_IN + n) = make_float2(v0, v1);
                }
            }
        }
    }
}

#define GEMM_SMEM_96  (2 * (2 * ATILE_B + 2 * 96 * TSTRB))    // 71680
#define GEMM_SMEM_128 (2 * (2 * ATILE_B + 2 * 128 * TSTRB))   // 81920

// ===========================================================================
// HMMA flash attention. BQ=128, BK=64; 108 KB smem -> 2 CTAs/SM, single wave.
// ===========================================================================
#define BQ 128
#define BK 64
#define KSTR 144
#define VSTR 144
#define QBUF  (128 * KSTR)
#define OFF_Q   0
#define KBUF  (BK * KSTR)
#define OFF_K0  (2 * QBUF)
#define OFF_K1  (OFF_K0 + 2 * KBUF)
#define VBUF  (E * VSTR)
#define OFF_VT0 (OFF_K1 + 2 * KBUF)
#define OFF_VT1 (OFF_VT0 + 2 * VBUF)
#define ATTN_SMEM (OFF_VT1 + 2 * VBUF)       // 110592

__global__ __launch_bounds__(256, 2) void attn_kernel()
{
    extern __shared__ __align__(16) char smem[];
    const uint32_t smb = smem_u32(smem);
    const int tid = threadIdx.x, wid = tid >> 5, lane = tid & 31;
    const int grp = lane >> 2, qid = lane & 3;
    const int h = blockIdx.y;
    const int q0 = blockIdx.x * BQ;
    const int wm = wid * 16;

    const __nv_bfloat16* gQh = g_Qh + ((size_t)h * N_TOK + q0) * E;
    const __nv_bfloat16* gQl = g_Ql + ((size_t)h * N_TOK + q0) * E;
    const __nv_bfloat16* gKh = g_Kh + (size_t)h * N_TOK * E;
    const __nv_bfloat16* gKl = g_Kl + (size_t)h * N_TOK * E;
    const __nv_bfloat16* gVth = g_Vth + (size_t)h * E * N_TOK;
    const __nv_bfloat16* gVtl = g_Vtl + (size_t)h * E * N_TOK;

    const int arow = ((lane >> 3) & 1) * 8 + (lane & 7);
    const int acol = ((lane >> 4) & 1) * 16;
    const int brow = ((lane >> 4) & 1) * 8 + (lane & 7);
    const int bcol = ((lane >> 3) & 1) * 16;

    auto load_kv = [&](uint32_t koff, uint32_t voff, int c) {
        #pragma unroll
        for (int i = 0; i < 4; i++) {
            int idx = i * 256 + tid;
            int t = idx >> 9, w = idx & 511, row = w >> 3, ch = w & 7;
            const __nv_bfloat16* S = (t ? gKl : gKh);
            cp16(smb + koff + t * KBUF + row * KSTR + ch * 16,
                 S + ((size_t)c * BK + row) * E + ch * 8);
            const __nv_bfloat16* SV = (t ? gVtl : gVth);
            cp16(smb + voff + t * VBUF + row * VSTR + ch * 16,
                 SV + (size_t)row * N_TOK + c * BK + ch * 8);
        }
    };

    // prologue: Q (128 rows x 8 chunks, BOTH hi and lo per idx) + chunk 0
    #pragma unroll
    for (int i = 0; i < 4; i++) {
        int idx = i * 256 + tid;
        int row = idx >> 3, ch = idx & 7;
        uint32_t so = row * KSTR + ch * 16;
        size_t  go = (size_t)row * E + ch * 8;
        cp16(smb + OFF_Q + so,        gQh + go);
        cp16(smb + OFF_Q + QBUF + so, gQl + go);
    }
    load_kv(OFF_K0, OFF_VT0, 0);
    CP_COMMIT();

    float accO[8][4] = {};
    float m0 = -1e30f, m1 = -1e30f, l0 = 0.f, l1 = 0.f;

    CP_WAIT0();
    __syncthreads();

    for (int c = 0; c < N_TOK / BK; c++) {
        const uint32_t kb  = smb + ((c & 1) ? OFF_K1 : OFF_K0);
        const uint32_t vtb = smb + ((c & 1) ? OFF_VT1 : OFF_VT0);

        // ---- S = Q K^T
        float accS[8][4] = {};
        #pragma unroll
        for (int k16 = 0; k16 < 4; k16++) {
            uint32_t ah[4], al[4];
            const uint32_t aaddr = smb + OFF_Q + (wm + arow) * KSTR + k16 * 32 + acol;
            ldsm_x4(ah, aaddr);
            ldsm_x4(al, aaddr + QBUF);
            #pragma unroll
            for (int np = 0; np < 4; np++) {
                uint32_t bh[4], bl[4];
                const uint32_t baddr = kb + (np * 16 + brow) * KSTR + k16 * 32 + bcol;
                ldsm_x4(bh, baddr);
                ldsm_x4(bl, baddr + KBUF);
                mma_bf16(accS[2*np],   ah, bh);
                mma_bf16(accS[2*np],   ah, bl);
                mma_bf16(accS[2*np],   al, bh);
                mma_bf16(accS[2*np+1], ah, bh + 2);
                mma_bf16(accS[2*np+1], ah, bl + 2);
                mma_bf16(accS[2*np+1], al, bh + 2);
            }
        }

        // ---- prefetch next chunk
        if (c + 1 < N_TOK / BK) {
            load_kv((c & 1) ? OFF_K0 : OFF_K1, (c & 1) ? OFF_VT0 : OFF_VT1, c + 1);
            CP_COMMIT();
        }

        // ---- online softmax
        float mx0 = -1e30f, mx1 = -1e30f;
        #pragma unroll
        for (int n8 = 0; n8 < 8; n8++) {
            mx0 = fmaxf(mx0, fmaxf(accS[n8][0], accS[n8][1]));
            mx1 = fmaxf(mx1, fmaxf(accS[n8][2], accS[n8][3]));
        }
        mx0 = fmaxf(mx0, __shfl_xor_sync(0xffffffff, mx0, 1));
        mx0 = fmaxf(mx0, __shfl_xor_sync(0xffffffff, mx0, 2));
        mx1 = fmaxf(mx1, __shfl_xor_sync(0xffffffff, mx1, 1));
        mx1 = fmaxf(mx1, __shfl_xor_sync(0xffffffff, mx1, 2));
        float mn0 = fmaxf(m0, mx0), mn1 = fmaxf(m1, mx1);
        float al0 = fast_exp((m0 - mn0) * 0.125f);
        float al1 = fast_exp((m1 - mn1) * 0.125f);
        m0 = mn0; m1 = mn1;
        float s0 = 0.f, s1 = 0.f;
        #pragma unroll
        for (int n8 = 0; n8 < 8; n8++) {
            accS[n8][0] = fast_exp((accS[n8][0] - m0) * 0.125f);
            accS[n8][1] = fast_exp((accS[n8][1] - m0) * 0.125f);
            accS[n8][2] = fast_exp((accS[n8][2] - m1) * 0.125f);
            accS[n8][3] = fast_exp((accS[n8][3] - m1) * 0.125f);
            s0 += accS[n8][0] + accS[n8][1];
            s1 += accS[n8][2] + accS[n8][3];
        }
        s0 += __shfl_xor_sync(0xffffffff, s0, 1);
        s0 += __shfl_xor_sync(0xffffffff, s0, 2);
        s1 += __shfl_xor_sync(0xffffffff, s1, 1);
        s1 += __shfl_xor_sync(0xffffffff, s1, 2);
        l0 = l0 * al0 + s0;
        l1 = l1 * al1 + s1;
        #pragma unroll
        for (int n8v = 0; n8v < 8; n8v++) {
            accO[n8v][0] *= al0; accO[n8v][1] *= al0;
            accO[n8v][2] *= al1; accO[n8v][3] *= al1;
        }

        // ---- PV
        #pragma unroll
        for (int kk = 0; kk < 4; kk++) {
            uint32_t ah[4], al[4];
            split_pack(accS[2 * kk][0],     accS[2 * kk][1],     ah[0], al[0]);
            split_pack(accS[2 * kk][2],     accS[2 * kk][3],     ah[1], al[1]);
            split_pack(accS[2 * kk + 1][0], accS[2 * kk + 1][1], ah[2], al[2]);
            split_pack(accS[2 * kk + 1][2], accS[2 * kk + 1][3], ah[3], al[3]);
            #pragma unroll
            for (int np = 0; np < 4; np++) {
                uint32_t bh[4], bl[4];
                const uint32_t baddr = vtb + (np * 16 + brow) * VSTR + kk * 32 + bcol;
                ldsm_x4(bh, baddr);
                ldsm_x4(bl, baddr + VBUF);
                mma_bf16(accO[2*np],   ah, bh);
                mma_bf16(accO[2*np],   ah, bl);
                mma_bf16(accO[2*np],   al, bh);
                mma_bf16(accO[2*np+1], ah, bh + 2);
                mma_bf16(accO[2*np+1], ah, bl + 2);
                mma_bf16(accO[2*np+1], al, bh + 2);
            }
        }

        if (c + 1 < N_TOK / BK) {
            CP_WAIT0();
            __syncthreads();
        }
    }

    // ---- epilogue
    float inv0 = 1.f / l0, inv1 = 1.f / l1;
    const int row0 = q0 + wm + grp, row1 = row0 + 8;
    #pragma unroll
    for (int n8v = 0; n8v < 8; n8v++) {
        int colb = h * E + n8v * 8 + qid * 2;
        uint32_t wh, wl;
        split_pack(accO[n8v][0] * inv0, accO[n8v][1] * inv0, wh, wl);
        *(uint32_t*)(g_ctxh + (size_t)row0 * D_IN + colb) = wh;
        *(uint32_t*)(g_ctxl + (size_t)row0 * D_IN + colb) = wl;
        split_pack(accO[n8v][2] * inv1, accO[n8v][3] * inv1, wh, wl);
        *(uint32_t*)(g_ctxh + (size_t)row1 * D_IN + colb) = wh;
        *(uint32_t*)(g_ctxl + (size_t)row1 * D_IN + colb) = wl;
    }
}

// ===========================================================================
extern "C" void kernel_launch(void* const* d_in, const int* in_sizes, int n_in,
                              void* d_out, int out_size)
{
    const float* x  = (const float*)d_in[0];
    const float* Wq = (const float*)d_in[1];
    const float* Wk = (const float*)d_in[2];
    const float* Wv = (const float*)d_in[3];
    const float* Wo = (const float*)d_in[4];
    float* out = (float*)d_out;
    (void)in_sizes; (void)n_in; (void)out_size;

    cudaFuncSetAttribute(attn_kernel,
                         cudaFuncAttributeMaxDynamicSharedMemorySize, ATTN_SMEM);
    cudaFuncSetAttribute(gemm_kernel<96>,
                         cudaFuncAttributeMaxDynamicSharedMemorySize, GEMM_SMEM_96);
    cudaFuncSetAttribute(gemm_kernel<128>,
                         cudaFuncAttributeMaxDynamicSharedMemorySize, GEMM_SMEM_128);

    static __nv_bfloat16 *p_xh = nullptr, *p_xl, *p_Wth, *p_Wtl, *p_Woth, *p_Wotl, *p_ch, *p_cl;
    if (!p_xh) {
        cudaGetSymbolAddress((void**)&p_xh,  g_xh);
        cudaGetSymbolAddress((void**)&p_xl,  g_xl);
        cudaGetSymbolAddress((void**)&p_Wth, g_Wth);
        cudaGetSymbolAddress((void**)&p_Wtl, g_Wtl);
        cudaGetSymbolAddress((void**)&p_Woth, g_Woth);
        cudaGetSymbolAddress((void**)&p_Wotl, g_Wotl);
        cudaGetSymbolAddress((void**)&p_ch,  g_ctxh);
        cudaGetSymbolAddress((void**)&p_cl,  g_ctxl);
    }

    // prep
    split_x_kernel<<<(N_TOK * D_IN) / (256 * 4), 256>>>(x);
    dim3 gw(D_IN / 64, NH, 3);
    conv_w_kernel<<<gw, 256>>>(Wq, Wk, Wv);
    dim3 gwo(D_IN / 64, D_IN / 64);
    conv_wo_kernel<<<gwo, 256>>>(Wo);

    // QKV (BN=96: grid 32 x 16)
    dim3 g1(3072 / 96, N_TOK / 128);
    gemm_kernel<96><<<g1, 256, GEMM_SMEM_96>>>(p_xh, p_xl, p_Wth, p_Wtl, 0, nullptr);

    // HMMA flash attention
    dim3 g2(N_TOK / BQ, NH);
    attn_kernel<<<g2, 256, ATTN_SMEM>>>();

    // out = ctx @ Wo (BN=128: grid 8 x 16)
    dim3 g3(D_IN / 128, N_TOK / 128);
    gemm_kernel<128><<<g3, 256, GEMM_SMEM_128>>>(p_ch, p_cl, p_Woth, p_Wotl, 1, out);
}